// round 2
// baseline (speedup 1.0000x reference)
#include <cuda_runtime.h>
#include <math.h>

// GPT-2 small config
#define BSZ   2
#define TSEQ  1024
#define CDIM  768
#define FFDIM 3072
#define NHEAD 12
#define NLAYER 12
#define DHEAD 64
#define VOCAB 50257
#define NROW  (BSZ * TSEQ)   // 2048

// ---------------------------------------------------------------------------
// Scratch (device globals — no allocation allowed)
// ---------------------------------------------------------------------------
__device__ float g_x  [NROW * CDIM];          // residual stream
__device__ float g_h  [NROW * CDIM];          // LN output
__device__ float g_qkv[NROW * 3 * CDIM];      // qkv projection
__device__ float g_att[NROW * CDIM];          // attention output
__device__ float g_ffn[NROW * FFDIM];         // FFN intermediate

// ---------------------------------------------------------------------------
// Embedding: x[n,c] = tok_embed[tokens[n],c] + pos_embed[n%T, c]
// ---------------------------------------------------------------------------
__global__ void embed_kernel(const int* __restrict__ tokens,
                             const float* __restrict__ tok,
                             const float* __restrict__ pos,
                             float* __restrict__ x) {
    int n = blockIdx.x;
    int t = n % TSEQ;
    int tk = tokens[n];
    const float* tr = tok + (size_t)tk * CDIM;
    const float* pr = pos + (size_t)t * CDIM;
    float* xr = x + (size_t)n * CDIM;
    for (int c = threadIdx.x; c < CDIM; c += blockDim.x)
        xr[c] = tr[c] + pr[c];
}

// ---------------------------------------------------------------------------
// LayerNorm (block per row, 256 threads)
// ---------------------------------------------------------------------------
__global__ void ln_kernel(const float* __restrict__ x,
                          const float* __restrict__ w,
                          const float* __restrict__ b,
                          float* __restrict__ out) {
    int n = blockIdx.x;
    const float* xr = x + (size_t)n * CDIM;
    float s = 0.f, s2 = 0.f;
    for (int c = threadIdx.x; c < CDIM; c += blockDim.x) {
        float v = xr[c];
        s += v; s2 += v * v;
    }
    __shared__ float red[64];
    #pragma unroll
    for (int o = 16; o; o >>= 1) {
        s  += __shfl_xor_sync(~0u, s,  o);
        s2 += __shfl_xor_sync(~0u, s2, o);
    }
    int wid = threadIdx.x >> 5, lid = threadIdx.x & 31;
    if (lid == 0) { red[wid] = s; red[wid + 32] = s2; }
    __syncthreads();
    if (threadIdx.x == 0) {
        float ts = 0.f, ts2 = 0.f;
        int nw = blockDim.x >> 5;
        for (int i = 0; i < nw; i++) { ts += red[i]; ts2 += red[i + 32]; }
        float m = ts / CDIM;
        float var = ts2 / CDIM - m * m;
        red[0] = m;
        red[1] = rsqrtf(var + 1e-5f);
    }
    __syncthreads();
    float m = red[0], r = red[1];
    float* orow = out + (size_t)n * CDIM;
    for (int c = threadIdx.x; c < CDIM; c += blockDim.x)
        orow[c] = (xr[c] - m) * r * w[c] + b[c];
}

// ---------------------------------------------------------------------------
// Generic NT SGEMM:  C[n,m] = sum_k A[n,k] * W[m,k]  (+bias, +GELU, +residual)
// A: [N,K] row-major, W: [M,K] row-major. K must be a multiple of 16 (it is:
// 768 or 3072). N multiple of 128 (2048). M may be ragged (50257).
// 128x128 tile, BK=16, 256 threads, 8x8 per-thread microtile.
// ---------------------------------------------------------------------------
#define BM 128
#define BN 128
#define BK 16
#define TM 8
#define TN 8

__global__ __launch_bounds__(256, 1)
void gemm_nt_kernel(const float* __restrict__ A,
                    const float* __restrict__ W,
                    const float* __restrict__ bias,      // may be null
                    const float* __restrict__ res,       // may be null, [N,M]
                    float* __restrict__ C,
                    int N, int M, int K, int gelu) {
    __shared__ float As[BK][BM];
    __shared__ float Bs[BK][BN];

    int tid = threadIdx.x;
    int bm = blockIdx.y * BM;   // row base (N dim)
    int bn = blockIdx.x * BN;   // col base (M dim)
    int tx = tid & 15, ty = tid >> 4;

    float acc[TM][TN];
    #pragma unroll
    for (int i = 0; i < TM; i++)
        #pragma unroll
        for (int j = 0; j < TN; j++) acc[i][j] = 0.f;

    for (int k0 = 0; k0 < K; k0 += BK) {
        // Load A tile (128 x 16) = 512 float4, transposed into As[k][n]
        #pragma unroll
        for (int i = 0; i < 2; i++) {
            int f = tid + i * 256;
            int row = f >> 2;
            int c4  = (f & 3) * 4;
            float4 v = *(const float4*)(A + (size_t)(bm + row) * K + k0 + c4);
            As[c4 + 0][row] = v.x; As[c4 + 1][row] = v.y;
            As[c4 + 2][row] = v.z; As[c4 + 3][row] = v.w;
        }
        // Load W tile (128 x 16), guard ragged M
        #pragma unroll
        for (int i = 0; i < 2; i++) {
            int f = tid + i * 256;
            int row = f >> 2;
            int c4  = (f & 3) * 4;
            int m = bn + row;
            float4 v = make_float4(0.f, 0.f, 0.f, 0.f);
            if (m < M) v = *(const float4*)(W + (size_t)m * K + k0 + c4);
            Bs[c4 + 0][row] = v.x; Bs[c4 + 1][row] = v.y;
            Bs[c4 + 2][row] = v.z; Bs[c4 + 3][row] = v.w;
        }
        __syncthreads();

        #pragma unroll
        for (int kk = 0; kk < BK; kk++) {
            float a[TM], bb[TN];
            #pragma unroll
            for (int i = 0; i < TM; i++) a[i] = As[kk][ty * TM + i];
            #pragma unroll
            for (int j = 0; j < TN; j++) bb[j] = Bs[kk][tx * TN + j];
            #pragma unroll
            for (int i = 0; i < TM; i++)
                #pragma unroll
                for (int j = 0; j < TN; j++)
                    acc[i][j] += a[i] * bb[j];
        }
        __syncthreads();
    }

    // Epilogue
    #pragma unroll
    for (int i = 0; i < TM; i++) {
        int n = bm + ty * TM + i;
        #pragma unroll
        for (int j = 0; j < TN; j++) {
            int m = bn + tx * TN + j;
            if (m < M) {
                float v = acc[i][j];
                if (bias) v += bias[m];
                if (gelu) {
                    float u = v;
                    v = 0.5f * u * (1.f + tanhf(0.7978845608028654f *
                                                (u + 0.044715f * u * u * u)));
                }
                size_t idx = (size_t)n * M + m;
                if (res) v += res[idx];
                C[idx] = v;
            }
        }
    }
}

// ---------------------------------------------------------------------------
// Attention: block per (query row t, batch-head). 128 threads.
// scores[j] = q . k_j * 1/8 for j <= t, stable softmax, o = P @ V.
// qkv layout per row n: [ q(0..767) | k(768..1535) | v(1536..2303) ]
// ---------------------------------------------------------------------------
__global__ void attn_kernel(const float* __restrict__ qkv,
                            float* __restrict__ out) {
    int t  = blockIdx.x;
    int bh = blockIdx.y;
    int b  = bh / NHEAD, h = bh % NHEAD;
    int Lq = t + 1;
    int n  = b * TSEQ + t;

    __shared__ float qs[DHEAD];
    __shared__ float sc[TSEQ];
    __shared__ float red[4];
    __shared__ float obuf[2][DHEAD];

    int tid = threadIdx.x;
    const float* qp = qkv + (size_t)n * (3 * CDIM) + h * DHEAD;
    if (tid < DHEAD) qs[tid] = qp[tid];
    __syncthreads();

    // Pass 1: scores + local max
    float lmax = -1e30f;
    for (int j = tid; j < Lq; j += 128) {
        const float4* kp = (const float4*)(qkv + (size_t)(b * TSEQ + j) * (3 * CDIM)
                                           + CDIM + h * DHEAD);
        float s = 0.f;
        #pragma unroll
        for (int d4 = 0; d4 < DHEAD / 4; d4++) {
            float4 kv = kp[d4];
            int d = d4 * 4;
            s += qs[d] * kv.x + qs[d + 1] * kv.y + qs[d + 2] * kv.z + qs[d + 3] * kv.w;
        }
        s *= 0.125f;   // 1/sqrt(64)
        sc[j] = s;
        lmax = fmaxf(lmax, s);
    }
    #pragma unroll
    for (int o = 16; o; o >>= 1) lmax = fmaxf(lmax, __shfl_xor_sync(~0u, lmax, o));
    if ((tid & 31) == 0) red[tid >> 5] = lmax;
    __syncthreads();
    float mx = fmaxf(fmaxf(red[0], red[1]), fmaxf(red[2], red[3]));
    __syncthreads();   // everyone has mx before red is reused

    // Pass 2: exp + sum
    float lsum = 0.f;
    for (int j = tid; j < Lq; j += 128) {
        float p = expf(sc[j] - mx);
        sc[j] = p;
        lsum += p;
    }
    #pragma unroll
    for (int o = 16; o; o >>= 1) lsum += __shfl_xor_sync(~0u, lsum, o);
    if ((tid & 31) == 0) red[tid >> 5] = lsum;
    __syncthreads();
    float denom = red[0] + red[1] + red[2] + red[3];

    // Pass 3: o[d] = sum_j p_j * V[j,d]; split j over two halves of the block
    int d = tid & 63, half = tid >> 6;
    float oacc = 0.f;
    for (int j = half; j < Lq; j += 2) {
        const float* vp = qkv + (size_t)(b * TSEQ + j) * (3 * CDIM)
                          + 2 * CDIM + h * DHEAD;
        oacc += sc[j] * vp[d];
    }
    obuf[half][d] = oacc;
    __syncthreads();
    if (tid < DHEAD)
        out[(size_t)n * CDIM + h * DHEAD + tid] =
            (obuf[0][tid] + obuf[1][tid]) / denom;
}

// ---------------------------------------------------------------------------
// Launcher
// ---------------------------------------------------------------------------
extern "C" void kernel_launch(void* const* d_in, const int* in_sizes, int n_in,
                              void* d_out, int out_size) {
    const int*   tokens    = (const int*)  d_in[0];
    const float* tok_embed = (const float*)d_in[1];
    const float* pos_embed = (const float*)d_in[2];
    const float* ln1_w     = (const float*)d_in[3];
    const float* ln1_b     = (const float*)d_in[4];
    const float* qkv_w     = (const float*)d_in[5];
    const float* qkv_b     = (const float*)d_in[6];
    const float* proj_w    = (const float*)d_in[7];
    const float* proj_b    = (const float*)d_in[8];
    const float* ln2_w     = (const float*)d_in[9];
    const float* ln2_b     = (const float*)d_in[10];
    const float* fc_w      = (const float*)d_in[11];
    const float* fc_b      = (const float*)d_in[12];
    const float* fc2_w     = (const float*)d_in[13];
    const float* fc2_b     = (const float*)d_in[14];
    const float* lnf_w     = (const float*)d_in[15];
    const float* lnf_b     = (const float*)d_in[16];
    float* logits = (float*)d_out;

    float *x, *h, *qkv, *att, *ffn;
    cudaGetSymbolAddress((void**)&x,   g_x);
    cudaGetSymbolAddress((void**)&h,   g_h);
    cudaGetSymbolAddress((void**)&qkv, g_qkv);
    cudaGetSymbolAddress((void**)&att, g_att);
    cudaGetSymbolAddress((void**)&ffn, g_ffn);

    embed_kernel<<<NROW, 256>>>(tokens, tok_embed, pos_embed, x);

    const int NB = NROW / BM;   // 16 row-blocks
    for (int l = 0; l < NLAYER; l++) {
        const float* l1w = ln1_w  + (size_t)l * CDIM;
        const float* l1b = ln1_b  + (size_t)l * CDIM;
        const float* qw  = qkv_w  + (size_t)l * 3 * CDIM * CDIM;
        const float* qb  = qkv_b  + (size_t)l * 3 * CDIM;
        const float* pw  = proj_w + (size_t)l * CDIM * CDIM;
        const float* pb  = proj_b + (size_t)l * CDIM;
        const float* l2w = ln2_w  + (size_t)l * CDIM;
        const float* l2b = ln2_b  + (size_t)l * CDIM;
        const float* fw  = fc_w   + (size_t)l * FFDIM * CDIM;
        const float* fb  = fc_b   + (size_t)l * FFDIM;
        const float* f2w = fc2_w  + (size_t)l * CDIM * FFDIM;
        const float* f2b = fc2_b  + (size_t)l * CDIM;

        // LN1
        ln_kernel<<<NROW, 256>>>(x, l1w, l1b, h);
        // QKV: [2048,768] x [2304,768]^T
        gemm_nt_kernel<<<dim3(3 * CDIM / BN, NB), 256>>>(
            h, qw, qb, nullptr, qkv, NROW, 3 * CDIM, CDIM, 0);
        // Attention
        attn_kernel<<<dim3(TSEQ, BSZ * NHEAD), 128>>>(qkv, att);
        // Proj + residual (in-place into x)
        gemm_nt_kernel<<<dim3(CDIM / BN, NB), 256>>>(
            att, pw, pb, x, x, NROW, CDIM, CDIM, 0);
        // LN2
        ln_kernel<<<NROW, 256>>>(x, l2w, l2b, h);
        // FC + GELU
        gemm_nt_kernel<<<dim3(FFDIM / BN, NB), 256>>>(
            h, fw, fb, nullptr, ffn, NROW, FFDIM, CDIM, 1);
        // FC2 + residual (in-place into x)
        gemm_nt_kernel<<<dim3(CDIM / BN, NB), 256>>>(
            ffn, f2w, f2b, x, x, NROW, CDIM, FFDIM, 0);
    }

    // Final LN
    ln_kernel<<<NROW, 256>>>(x, lnf_w, lnf_b, h);
    // LM head: [2048,768] x [50257,768]^T  -> logits
    gemm_nt_kernel<<<dim3((VOCAB + BN - 1) / BN, NB), 256>>>(
        h, tok_embed, nullptr, nullptr, logits, NROW, VOCAB, CDIM, 0);
}

// round 3
// speedup vs baseline: 1.5946x; 1.5946x over previous
#include <cuda_runtime.h>
#include <math.h>

// GPT-2 small config
#define BSZ   2
#define TSEQ  1024
#define CDIM  768
#define FFDIM 3072
#define NHEAD 12
#define NLAYER 12
#define DHEAD 64
#define VOCAB 50257
#define NROW  (BSZ * TSEQ)   // 2048

// ---------------------------------------------------------------------------
// Scratch (device globals — no allocation allowed)
// ---------------------------------------------------------------------------
__device__ float g_x  [NROW * CDIM];          // residual stream
__device__ float g_h  [NROW * CDIM];          // LN output
__device__ float g_qkv[NROW * 3 * CDIM];      // qkv projection
__device__ float g_att[NROW * CDIM];          // attention output
__device__ float g_ffn[NROW * FFDIM];         // FFN intermediate

// ---------------------------------------------------------------------------
// Embedding
// ---------------------------------------------------------------------------
__global__ void embed_kernel(const int* __restrict__ tokens,
                             const float* __restrict__ tok,
                             const float* __restrict__ pos,
                             float* __restrict__ x) {
    int n = blockIdx.x;
    int t = n % TSEQ;
    int tk = tokens[n];
    const float* tr = tok + (size_t)tk * CDIM;
    const float* pr = pos + (size_t)t * CDIM;
    float* xr = x + (size_t)n * CDIM;
    for (int c = threadIdx.x; c < CDIM; c += blockDim.x)
        xr[c] = tr[c] + pr[c];
}

// ---------------------------------------------------------------------------
// LayerNorm (block per row, 256 threads)
// ---------------------------------------------------------------------------
__global__ void ln_kernel(const float* __restrict__ x,
                          const float* __restrict__ w,
                          const float* __restrict__ b,
                          float* __restrict__ out) {
    int n = blockIdx.x;
    const float* xr = x + (size_t)n * CDIM;
    float s = 0.f, s2 = 0.f;
    for (int c = threadIdx.x; c < CDIM; c += blockDim.x) {
        float v = xr[c];
        s += v; s2 += v * v;
    }
    __shared__ float red[64];
    #pragma unroll
    for (int o = 16; o; o >>= 1) {
        s  += __shfl_xor_sync(~0u, s,  o);
        s2 += __shfl_xor_sync(~0u, s2, o);
    }
    int wid = threadIdx.x >> 5, lid = threadIdx.x & 31;
    if (lid == 0) { red[wid] = s; red[wid + 32] = s2; }
    __syncthreads();
    if (threadIdx.x == 0) {
        float ts = 0.f, ts2 = 0.f;
        int nw = blockDim.x >> 5;
        for (int i = 0; i < nw; i++) { ts += red[i]; ts2 += red[i + 32]; }
        float m = ts / CDIM;
        float var = ts2 / CDIM - m * m;
        red[0] = m;
        red[1] = rsqrtf(var + 1e-5f);
    }
    __syncthreads();
    float m = red[0], r = red[1];
    float* orow = out + (size_t)n * CDIM;
    for (int c = threadIdx.x; c < CDIM; c += blockDim.x)
        orow[c] = (xr[c] - m) * r * w[c] + b[c];
}

// ---------------------------------------------------------------------------
// TF32 helpers
// ---------------------------------------------------------------------------
__device__ __forceinline__ float f2tf32(float x) {
    asm("cvt.rna.tf32.f32 %0, %0;" : "+f"(x));
    return x;
}

__device__ __forceinline__ void mma_tf32(float (&d)[4],
                                         const float (&a)[4],
                                         const float (&b)[2]) {
    asm volatile(
        "mma.sync.aligned.m16n8k8.row.col.f32.tf32.tf32.f32 "
        "{%0,%1,%2,%3}, {%4,%5,%6,%7}, {%8,%9}, {%0,%1,%2,%3};\n"
        : "+f"(d[0]), "+f"(d[1]), "+f"(d[2]), "+f"(d[3])
        : "r"(__float_as_uint(a[0])), "r"(__float_as_uint(a[1])),
          "r"(__float_as_uint(a[2])), "r"(__float_as_uint(a[3])),
          "r"(__float_as_uint(b[0])), "r"(__float_as_uint(b[1])));
}

// ---------------------------------------------------------------------------
// TF32 NT GEMM:  C[n,m] = sum_k A[n,k] * W[m,k]  (+bias, +GELU, +residual)
// A:[N,K], W:[M,K] row-major. K % 16 == 0. N % 128 == 0. M may be ragged.
// 128x128x16 tile, 256 threads = 8 warps (2x4), warp tile 64x32,
// m16n8k8 tf32 MMA, double-buffered smem.
// ---------------------------------------------------------------------------
#define BM 128
#define BN 128
#define BK 16
#define BK2 (BK + 2)   // smem row stride (pad 2)

__global__ __launch_bounds__(256)
void gemm_tf32_kernel(const float* __restrict__ A,
                      const float* __restrict__ W,
                      const float* __restrict__ bias,   // may be null
                      const float* __restrict__ res,    // may be null, [N,M]
                      float* __restrict__ C,
                      int N, int M, int K, int gelu) {
    __shared__ float As[2][BM][BK2];
    __shared__ float Bs[2][BN][BK2];

    const int tid  = threadIdx.x;
    const int lane = tid & 31;
    const int wid  = tid >> 5;
    const int g    = lane >> 2;      // group id 0..7
    const int tig  = lane & 3;       // thread in group 0..3
    const int warp_m = wid >> 2;     // 0..1
    const int warp_n = wid & 3;      // 0..3
    const int bm = blockIdx.y * BM;
    const int bn = blockIdx.x * BN;

    // gmem tile load mapping: f = tid + i*256; row = f>>2; c4 = (f&3)*4
    const int lr0 = tid >> 2;         // 0..63
    const int lc4 = (tid & 3) * 4;    // 0,4,8,12

    float acc[4][4][4];
    #pragma unroll
    for (int mt = 0; mt < 4; mt++)
        #pragma unroll
        for (int nt = 0; nt < 4; nt++)
            #pragma unroll
            for (int r = 0; r < 4; r++) acc[mt][nt][r] = 0.f;

    const int KT = K / BK;

    // ---- prologue: tile 0 ----
    {
        #pragma unroll
        for (int i = 0; i < 2; i++) {
            int r = lr0 + i * 64;
            float4 va = *(const float4*)(A + (size_t)(bm + r) * K + lc4);
            As[0][r][lc4 + 0] = f2tf32(va.x);
            As[0][r][lc4 + 1] = f2tf32(va.y);
            As[0][r][lc4 + 2] = f2tf32(va.z);
            As[0][r][lc4 + 3] = f2tf32(va.w);
            int m = bn + r;
            float4 vb = make_float4(0.f, 0.f, 0.f, 0.f);
            if (m < M) vb = *(const float4*)(W + (size_t)m * K + lc4);
            Bs[0][r][lc4 + 0] = f2tf32(vb.x);
            Bs[0][r][lc4 + 1] = f2tf32(vb.y);
            Bs[0][r][lc4 + 2] = f2tf32(vb.z);
            Bs[0][r][lc4 + 3] = f2tf32(vb.w);
        }
    }
    __syncthreads();

    int buf = 0;
    for (int it = 0; it < KT; it++) {
        // prefetch next tile into registers
        float4 na[2], nb[2];
        const bool has_next = (it + 1 < KT);
        if (has_next) {
            int k0 = (it + 1) * BK;
            #pragma unroll
            for (int i = 0; i < 2; i++) {
                int r = lr0 + i * 64;
                na[i] = *(const float4*)(A + (size_t)(bm + r) * K + k0 + lc4);
                int m = bn + r;
                nb[i] = make_float4(0.f, 0.f, 0.f, 0.f);
                if (m < M) nb[i] = *(const float4*)(W + (size_t)m * K + k0 + lc4);
            }
        }

        // compute on current buffer: 2 k-steps of 8
        #pragma unroll
        for (int ks = 0; ks < 2; ks++) {
            const int kb = ks * 8;
            float a[4][4], b[4][2];
            #pragma unroll
            for (int mt = 0; mt < 4; mt++) {
                int m0 = warp_m * 64 + mt * 16;
                a[mt][0] = As[buf][m0 + g    ][kb + tig    ];
                a[mt][1] = As[buf][m0 + g + 8][kb + tig    ];
                a[mt][2] = As[buf][m0 + g    ][kb + tig + 4];
                a[mt][3] = As[buf][m0 + g + 8][kb + tig + 4];
            }
            #pragma unroll
            for (int nt = 0; nt < 4; nt++) {
                int n0 = warp_n * 32 + nt * 8;
                b[nt][0] = Bs[buf][n0 + g][kb + tig    ];
                b[nt][1] = Bs[buf][n0 + g][kb + tig + 4];
            }
            #pragma unroll
            for (int mt = 0; mt < 4; mt++)
                #pragma unroll
                for (int nt = 0; nt < 4; nt++)
                    mma_tf32(acc[mt][nt], a[mt], b[nt]);
        }

        // stage next tile into the other buffer
        if (has_next) {
            int nbuf = buf ^ 1;
            #pragma unroll
            for (int i = 0; i < 2; i++) {
                int r = lr0 + i * 64;
                As[nbuf][r][lc4 + 0] = f2tf32(na[i].x);
                As[nbuf][r][lc4 + 1] = f2tf32(na[i].y);
                As[nbuf][r][lc4 + 2] = f2tf32(na[i].z);
                As[nbuf][r][lc4 + 3] = f2tf32(na[i].w);
                Bs[nbuf][r][lc4 + 0] = f2tf32(nb[i].x);
                Bs[nbuf][r][lc4 + 1] = f2tf32(nb[i].y);
                Bs[nbuf][r][lc4 + 2] = f2tf32(nb[i].z);
                Bs[nbuf][r][lc4 + 3] = f2tf32(nb[i].w);
            }
        }
        __syncthreads();
        buf ^= 1;
    }

    // ---- epilogue ----
    #pragma unroll
    for (int mt = 0; mt < 4; mt++) {
        #pragma unroll
        for (int nt = 0; nt < 4; nt++) {
            int col = bn + warp_n * 32 + nt * 8 + 2 * tig;
            #pragma unroll
            for (int rr = 0; rr < 2; rr++) {
                int row = bm + warp_m * 64 + mt * 16 + g + rr * 8;
                float v0 = acc[mt][nt][rr * 2 + 0];
                float v1 = acc[mt][nt][rr * 2 + 1];
                if (bias) { v0 += bias[col]; if (col + 1 < M) v1 += bias[col + 1]; }
                if (gelu) {
                    float u = v0;
                    v0 = 0.5f * u * (1.f + tanhf(0.7978845608028654f *
                                                 (u + 0.044715f * u * u * u)));
                    u = v1;
                    v1 = 0.5f * u * (1.f + tanhf(0.7978845608028654f *
                                                 (u + 0.044715f * u * u * u)));
                }
                size_t idx = (size_t)row * M + col;
                if (col + 1 < M) {
                    if (res) { v0 += res[idx]; v1 += res[idx + 1]; }
                    C[idx]     = v0;
                    C[idx + 1] = v1;
                } else if (col < M) {
                    if (res) v0 += res[idx];
                    C[idx] = v0;
                }
            }
        }
    }
}

// ---------------------------------------------------------------------------
// Attention: block per (query row t, batch-head). 128 threads. fp32.
// ---------------------------------------------------------------------------
__global__ void attn_kernel(const float* __restrict__ qkv,
                            float* __restrict__ out) {
    int t  = blockIdx.x;
    int bh = blockIdx.y;
    int b  = bh / NHEAD, h = bh % NHEAD;
    int Lq = t + 1;
    int n  = b * TSEQ + t;

    __shared__ float qs[DHEAD];
    __shared__ float sc[TSEQ];
    __shared__ float red[4];
    __shared__ float obuf[2][DHEAD];

    int tid = threadIdx.x;
    const float* qp = qkv + (size_t)n * (3 * CDIM) + h * DHEAD;
    if (tid < DHEAD) qs[tid] = qp[tid];
    __syncthreads();

    float lmax = -1e30f;
    for (int j = tid; j < Lq; j += 128) {
        const float4* kp = (const float4*)(qkv + (size_t)(b * TSEQ + j) * (3 * CDIM)
                                           + CDIM + h * DHEAD);
        float s = 0.f;
        #pragma unroll
        for (int d4 = 0; d4 < DHEAD / 4; d4++) {
            float4 kv = kp[d4];
            int d = d4 * 4;
            s += qs[d] * kv.x + qs[d + 1] * kv.y + qs[d + 2] * kv.z + qs[d + 3] * kv.w;
        }
        s *= 0.125f;
        sc[j] = s;
        lmax = fmaxf(lmax, s);
    }
    #pragma unroll
    for (int o = 16; o; o >>= 1) lmax = fmaxf(lmax, __shfl_xor_sync(~0u, lmax, o));
    if ((tid & 31) == 0) red[tid >> 5] = lmax;
    __syncthreads();
    float mx = fmaxf(fmaxf(red[0], red[1]), fmaxf(red[2], red[3]));
    __syncthreads();

    float lsum = 0.f;
    for (int j = tid; j < Lq; j += 128) {
        float p = expf(sc[j] - mx);
        sc[j] = p;
        lsum += p;
    }
    #pragma unroll
    for (int o = 16; o; o >>= 1) lsum += __shfl_xor_sync(~0u, lsum, o);
    if ((tid & 31) == 0) red[tid >> 5] = lsum;
    __syncthreads();
    float denom = red[0] + red[1] + red[2] + red[3];

    int d = tid & 63, half = tid >> 6;
    float oacc = 0.f;
    for (int j = half; j < Lq; j += 2) {
        const float* vp = qkv + (size_t)(b * TSEQ + j) * (3 * CDIM)
                          + 2 * CDIM + h * DHEAD;
        oacc += sc[j] * vp[d];
    }
    obuf[half][d] = oacc;
    __syncthreads();
    if (tid < DHEAD)
        out[(size_t)n * CDIM + h * DHEAD + tid] =
            (obuf[0][tid] + obuf[1][tid]) / denom;
}

// ---------------------------------------------------------------------------
// Launcher
// ---------------------------------------------------------------------------
extern "C" void kernel_launch(void* const* d_in, const int* in_sizes, int n_in,
                              void* d_out, int out_size) {
    const int*   tokens    = (const int*)  d_in[0];
    const float* tok_embed = (const float*)d_in[1];
    const float* pos_embed = (const float*)d_in[2];
    const float* ln1_w     = (const float*)d_in[3];
    const float* ln1_b     = (const float*)d_in[4];
    const float* qkv_w     = (const float*)d_in[5];
    const float* qkv_b     = (const float*)d_in[6];
    const float* proj_w    = (const float*)d_in[7];
    const float* proj_b    = (const float*)d_in[8];
    const float* ln2_w     = (const float*)d_in[9];
    const float* ln2_b     = (const float*)d_in[10];
    const float* fc_w      = (const float*)d_in[11];
    const float* fc_b      = (const float*)d_in[12];
    const float* fc2_w     = (const float*)d_in[13];
    const float* fc2_b     = (const float*)d_in[14];
    const float* lnf_w     = (const float*)d_in[15];
    const float* lnf_b     = (const float*)d_in[16];
    float* logits = (float*)d_out;

    float *x, *h, *qkv, *att, *ffn;
    cudaGetSymbolAddress((void**)&x,   g_x);
    cudaGetSymbolAddress((void**)&h,   g_h);
    cudaGetSymbolAddress((void**)&qkv, g_qkv);
    cudaGetSymbolAddress((void**)&att, g_att);
    cudaGetSymbolAddress((void**)&ffn, g_ffn);

    embed_kernel<<<NROW, 256>>>(tokens, tok_embed, pos_embed, x);

    const int NB = NROW / BM;   // 16 row-blocks
    for (int l = 0; l < NLAYER; l++) {
        const float* l1w = ln1_w  + (size_t)l * CDIM;
        const float* l1b = ln1_b  + (size_t)l * CDIM;
        const float* qw  = qkv_w  + (size_t)l * 3 * CDIM * CDIM;
        const float* qb  = qkv_b  + (size_t)l * 3 * CDIM;
        const float* pw  = proj_w + (size_t)l * CDIM * CDIM;
        const float* pb  = proj_b + (size_t)l * CDIM;
        const float* l2w = ln2_w  + (size_t)l * CDIM;
        const float* l2b = ln2_b  + (size_t)l * CDIM;
        const float* fw  = fc_w   + (size_t)l * FFDIM * CDIM;
        const float* fb  = fc_b   + (size_t)l * FFDIM;
        const float* f2w = fc2_w  + (size_t)l * CDIM * FFDIM;
        const float* f2b = fc2_b  + (size_t)l * CDIM;

        ln_kernel<<<NROW, 256>>>(x, l1w, l1b, h);
        gemm_tf32_kernel<<<dim3(3 * CDIM / BN, NB), 256>>>(
            h, qw, qb, nullptr, qkv, NROW, 3 * CDIM, CDIM, 0);
        attn_kernel<<<dim3(TSEQ, BSZ * NHEAD), 128>>>(qkv, att);
        gemm_tf32_kernel<<<dim3(CDIM / BN, NB), 256>>>(
            att, pw, pb, x, x, NROW, CDIM, CDIM, 0);
        ln_kernel<<<NROW, 256>>>(x, l2w, l2b, h);
        gemm_tf32_kernel<<<dim3(FFDIM / BN, NB), 256>>>(
            h, fw, fb, nullptr, ffn, NROW, FFDIM, CDIM, 1);
        gemm_tf32_kernel<<<dim3(CDIM / BN, NB), 256>>>(
            ffn, f2w, f2b, x, x, NROW, CDIM, FFDIM, 0);
    }

    ln_kernel<<<NROW, 256>>>(x, lnf_w, lnf_b, h);
    gemm_tf32_kernel<<<dim3((VOCAB + BN - 1) / BN, NB), 256>>>(
        h, tok_embed, nullptr, nullptr, logits, NROW, VOCAB, CDIM, 0);
}

// round 4
// speedup vs baseline: 2.9536x; 1.8523x over previous
#include <cuda_runtime.h>
#include <math.h>

// GPT-2 small config
#define BSZ   2
#define TSEQ  1024
#define CDIM  768
#define FFDIM 3072
#define NHEAD 12
#define NLAYER 12
#define DHEAD 64
#define VOCAB 50257
#define NROW  (BSZ * TSEQ)   // 2048

// ---------------------------------------------------------------------------
// Scratch (device globals — no allocation allowed)
// ---------------------------------------------------------------------------
__device__ float g_x  [NROW * CDIM];          // residual stream
__device__ float g_h  [NROW * CDIM];          // LN output
__device__ float g_qkv[NROW * 3 * CDIM];      // qkv projection
__device__ float g_att[NROW * CDIM];          // attention output
__device__ float g_ffn[NROW * FFDIM];         // FFN intermediate

// ---------------------------------------------------------------------------
// Embedding
// ---------------------------------------------------------------------------
__global__ void embed_kernel(const int* __restrict__ tokens,
                             const float* __restrict__ tok,
                             const float* __restrict__ pos,
                             float* __restrict__ x) {
    int n = blockIdx.x;
    int t = n % TSEQ;
    int tk = tokens[n];
    const float* tr = tok + (size_t)tk * CDIM;
    const float* pr = pos + (size_t)t * CDIM;
    float* xr = x + (size_t)n * CDIM;
    for (int c = threadIdx.x; c < CDIM; c += blockDim.x)
        xr[c] = tr[c] + pr[c];
}

// ---------------------------------------------------------------------------
// LayerNorm (block per row, 256 threads)
// ---------------------------------------------------------------------------
__global__ void ln_kernel(const float* __restrict__ x,
                          const float* __restrict__ w,
                          const float* __restrict__ b,
                          float* __restrict__ out) {
    int n = blockIdx.x;
    const float* xr = x + (size_t)n * CDIM;
    float s = 0.f, s2 = 0.f;
    for (int c = threadIdx.x; c < CDIM; c += blockDim.x) {
        float v = xr[c];
        s += v; s2 += v * v;
    }
    __shared__ float red[64];
    #pragma unroll
    for (int o = 16; o; o >>= 1) {
        s  += __shfl_xor_sync(~0u, s,  o);
        s2 += __shfl_xor_sync(~0u, s2, o);
    }
    int wid = threadIdx.x >> 5, lid = threadIdx.x & 31;
    if (lid == 0) { red[wid] = s; red[wid + 32] = s2; }
    __syncthreads();
    if (threadIdx.x == 0) {
        float ts = 0.f, ts2 = 0.f;
        int nw = blockDim.x >> 5;
        for (int i = 0; i < nw; i++) { ts += red[i]; ts2 += red[i + 32]; }
        float m = ts / CDIM;
        float var = ts2 / CDIM - m * m;
        red[0] = m;
        red[1] = rsqrtf(var + 1e-5f);
    }
    __syncthreads();
    float m = red[0], r = red[1];
    float* orow = out + (size_t)n * CDIM;
    for (int c = threadIdx.x; c < CDIM; c += blockDim.x)
        orow[c] = (xr[c] - m) * r * w[c] + b[c];
}

// ---------------------------------------------------------------------------
// TF32 helpers
// ---------------------------------------------------------------------------
__device__ __forceinline__ float f2tf32(float x) {
    asm("cvt.rna.tf32.f32 %0, %0;" : "+f"(x));
    return x;
}

__device__ __forceinline__ void mma_tf32(float (&d)[4],
                                         const float (&a)[4],
                                         const float (&b)[2]) {
    asm volatile(
        "mma.sync.aligned.m16n8k8.row.col.f32.tf32.tf32.f32 "
        "{%0,%1,%2,%3}, {%4,%5,%6,%7}, {%8,%9}, {%0,%1,%2,%3};\n"
        : "+f"(d[0]), "+f"(d[1]), "+f"(d[2]), "+f"(d[3])
        : "r"(__float_as_uint(a[0])), "r"(__float_as_uint(a[1])),
          "r"(__float_as_uint(a[2])), "r"(__float_as_uint(a[3])),
          "r"(__float_as_uint(b[0])), "r"(__float_as_uint(b[1])));
}

// ---------------------------------------------------------------------------
// TF32 NT GEMM (identical to R2 — known numerics)
// ---------------------------------------------------------------------------
#define BM 128
#define BN 128
#define BK 16
#define BK2 (BK + 2)

__global__ __launch_bounds__(256)
void gemm_tf32_kernel(const float* __restrict__ A,
                      const float* __restrict__ W,
                      const float* __restrict__ bias,
                      const float* __restrict__ res,
                      float* __restrict__ C,
                      int N, int M, int K, int gelu) {
    __shared__ float As[2][BM][BK2];
    __shared__ float Bs[2][BN][BK2];

    const int tid  = threadIdx.x;
    const int lane = tid & 31;
    const int wid  = tid >> 5;
    const int g    = lane >> 2;
    const int tig  = lane & 3;
    const int warp_m = wid >> 2;
    const int warp_n = wid & 3;
    const int bm = blockIdx.y * BM;
    const int bn = blockIdx.x * BN;

    const int lr0 = tid >> 2;
    const int lc4 = (tid & 3) * 4;

    float acc[4][4][4];
    #pragma unroll
    for (int mt = 0; mt < 4; mt++)
        #pragma unroll
        for (int nt = 0; nt < 4; nt++)
            #pragma unroll
            for (int r = 0; r < 4; r++) acc[mt][nt][r] = 0.f;

    const int KT = K / BK;

    {
        #pragma unroll
        for (int i = 0; i < 2; i++) {
            int r = lr0 + i * 64;
            float4 va = *(const float4*)(A + (size_t)(bm + r) * K + lc4);
            As[0][r][lc4 + 0] = f2tf32(va.x);
            As[0][r][lc4 + 1] = f2tf32(va.y);
            As[0][r][lc4 + 2] = f2tf32(va.z);
            As[0][r][lc4 + 3] = f2tf32(va.w);
            int m = bn + r;
            float4 vb = make_float4(0.f, 0.f, 0.f, 0.f);
            if (m < M) vb = *(const float4*)(W + (size_t)m * K + lc4);
            Bs[0][r][lc4 + 0] = f2tf32(vb.x);
            Bs[0][r][lc4 + 1] = f2tf32(vb.y);
            Bs[0][r][lc4 + 2] = f2tf32(vb.z);
            Bs[0][r][lc4 + 3] = f2tf32(vb.w);
        }
    }
    __syncthreads();

    int buf = 0;
    for (int it = 0; it < KT; it++) {
        float4 na[2], nb[2];
        const bool has_next = (it + 1 < KT);
        if (has_next) {
            int k0 = (it + 1) * BK;
            #pragma unroll
            for (int i = 0; i < 2; i++) {
                int r = lr0 + i * 64;
                na[i] = *(const float4*)(A + (size_t)(bm + r) * K + k0 + lc4);
                int m = bn + r;
                nb[i] = make_float4(0.f, 0.f, 0.f, 0.f);
                if (m < M) nb[i] = *(const float4*)(W + (size_t)m * K + k0 + lc4);
            }
        }

        #pragma unroll
        for (int ks = 0; ks < 2; ks++) {
            const int kb = ks * 8;
            float a[4][4], b[4][2];
            #pragma unroll
            for (int mt = 0; mt < 4; mt++) {
                int m0 = warp_m * 64 + mt * 16;
                a[mt][0] = As[buf][m0 + g    ][kb + tig    ];
                a[mt][1] = As[buf][m0 + g + 8][kb + tig    ];
                a[mt][2] = As[buf][m0 + g    ][kb + tig + 4];
                a[mt][3] = As[buf][m0 + g + 8][kb + tig + 4];
            }
            #pragma unroll
            for (int nt = 0; nt < 4; nt++) {
                int n0 = warp_n * 32 + nt * 8;
                b[nt][0] = Bs[buf][n0 + g][kb + tig    ];
                b[nt][1] = Bs[buf][n0 + g][kb + tig + 4];
            }
            #pragma unroll
            for (int mt = 0; mt < 4; mt++)
                #pragma unroll
                for (int nt = 0; nt < 4; nt++)
                    mma_tf32(acc[mt][nt], a[mt], b[nt]);
        }

        if (has_next) {
            int nbuf = buf ^ 1;
            #pragma unroll
            for (int i = 0; i < 2; i++) {
                int r = lr0 + i * 64;
                As[nbuf][r][lc4 + 0] = f2tf32(na[i].x);
                As[nbuf][r][lc4 + 1] = f2tf32(na[i].y);
                As[nbuf][r][lc4 + 2] = f2tf32(na[i].z);
                As[nbuf][r][lc4 + 3] = f2tf32(na[i].w);
                Bs[nbuf][r][lc4 + 0] = f2tf32(nb[i].x);
                Bs[nbuf][r][lc4 + 1] = f2tf32(nb[i].y);
                Bs[nbuf][r][lc4 + 2] = f2tf32(nb[i].z);
                Bs[nbuf][r][lc4 + 3] = f2tf32(nb[i].w);
            }
        }
        __syncthreads();
        buf ^= 1;
    }

    #pragma unroll
    for (int mt = 0; mt < 4; mt++) {
        #pragma unroll
        for (int nt = 0; nt < 4; nt++) {
            int col = bn + warp_n * 32 + nt * 8 + 2 * tig;
            #pragma unroll
            for (int rr = 0; rr < 2; rr++) {
                int row = bm + warp_m * 64 + mt * 16 + g + rr * 8;
                float v0 = acc[mt][nt][rr * 2 + 0];
                float v1 = acc[mt][nt][rr * 2 + 1];
                if (bias) { v0 += bias[col]; if (col + 1 < M) v1 += bias[col + 1]; }
                if (gelu) {
                    float u = v0;
                    v0 = 0.5f * u * (1.f + tanhf(0.7978845608028654f *
                                                 (u + 0.044715f * u * u * u)));
                    u = v1;
                    v1 = 0.5f * u * (1.f + tanhf(0.7978845608028654f *
                                                 (u + 0.044715f * u * u * u)));
                }
                size_t idx = (size_t)row * M + col;
                if (col + 1 < M) {
                    if (res) { v0 += res[idx]; v1 += res[idx + 1]; }
                    C[idx]     = v0;
                    C[idx + 1] = v1;
                } else if (col < M) {
                    if (res) v0 += res[idx];
                    C[idx] = v0;
                }
            }
        }
    }
}

// ---------------------------------------------------------------------------
// Flash-style tiled attention, fp32.
// Block: (b,h) x 128-query tile. 512 threads = 32 q-groups x 16 k/d-groups.
// Per thread: 4x4 S microtile (GEMM1), 4x4 O microtile (GEMM2).
// Smem tiles use XOR chunk swizzle: element (r, c) chunk cc=c/4 stored at
// chunk cc ^ ((r>>2)&15). Makes strided row reads conflict-free.
// ---------------------------------------------------------------------------
#define ATQ 128
#define ATK 64
#define LOG2E 1.44269504088896f

__device__ __forceinline__ int swz(int r, int dd) {   // dd = chunk index (c/4)
    return (r << 6) + (((dd) ^ ((r >> 2) & 15)) << 2);
}

__global__ __launch_bounds__(512)
void attn_kernel(const float* __restrict__ qkv, float* __restrict__ out) {
    extern __shared__ float sm[];
    float* Qs = sm;                       // 128 x 64 (swizzled)
    float* Ks = Qs + ATQ * DHEAD;         // 64 x 64
    float* Vs = Ks + ATK * DHEAD;         // 64 x 64
    float* Ps = Vs + ATK * DHEAD;         // 128 x 64

    const int qt = gridDim.x - 1 - blockIdx.x;   // heavy tiles first
    const int bh = blockIdx.y;
    const int b  = bh / NHEAD, h = bh % NHEAD;
    const int q0 = qt * ATQ;
    const int tid = threadIdx.x;
    const int qg = tid >> 4;     // 0..31
    const int kg = tid & 15;     // 0..15 (= dg in GEMM2)
    const size_t rstride = 3 * CDIM;

    // Load Q tile (pre-scaled by 1/sqrt(D))
    #pragma unroll
    for (int i = 0; i < 4; i++) {
        int f = i * 512 + tid;
        int r = f >> 4, cc = f & 15;
        float4 v = *(const float4*)(qkv + (size_t)(b * TSEQ + q0 + r) * rstride
                                    + h * DHEAD + cc * 4);
        v.x *= 0.125f; v.y *= 0.125f; v.z *= 0.125f; v.w *= 0.125f;
        *(float4*)&Qs[swz(r, cc)] = v;
    }

    float m[4], l[4];
    float4 O[4];
    #pragma unroll
    for (int i = 0; i < 4; i++) {
        m[i] = -1e30f; l[i] = 0.f; O[i] = make_float4(0.f, 0.f, 0.f, 0.f);
    }

    const int jtmax = (q0 + ATQ - 1) / ATK;
    for (int jt = 0; jt <= jtmax; jt++) {
        __syncthreads();
        // Stage K, V tiles (64 x 64 each)
        #pragma unroll
        for (int i = 0; i < 2; i++) {
            int f = i * 512 + tid;
            int r = f >> 4, cc = f & 15;
            const float* base = qkv + (size_t)(b * TSEQ + jt * ATK + r) * rstride
                                + h * DHEAD + cc * 4;
            *(float4*)&Ks[swz(r, cc)] = *(const float4*)(base + CDIM);
            *(float4*)&Vs[swz(r, cc)] = *(const float4*)(base + 2 * CDIM);
        }
        __syncthreads();

        // GEMM1: S(4q x 4k)
        float s[4][4];
        #pragma unroll
        for (int i = 0; i < 4; i++)
            #pragma unroll
            for (int j = 0; j < 4; j++) s[i][j] = 0.f;

        #pragma unroll
        for (int dd = 0; dd < DHEAD / 4; dd++) {
            float4 qv[4], kv[4];
            #pragma unroll
            for (int i = 0; i < 4; i++)
                qv[i] = *(const float4*)&Qs[swz(qg * 4 + i, dd)];
            #pragma unroll
            for (int j = 0; j < 4; j++)
                kv[j] = *(const float4*)&Ks[swz(kg * 4 + j, dd)];
            #pragma unroll
            for (int i = 0; i < 4; i++)
                #pragma unroll
                for (int j = 0; j < 4; j++)
                    s[i][j] += qv[i].x * kv[j].x + qv[i].y * kv[j].y
                             + qv[i].z * kv[j].z + qv[i].w * kv[j].w;
        }

        // Causal mask
        #pragma unroll
        for (int i = 0; i < 4; i++) {
            int qgl = q0 + qg * 4 + i;
            #pragma unroll
            for (int j = 0; j < 4; j++) {
                int jgl = jt * ATK + kg * 4 + j;
                if (jgl > qgl) s[i][j] = -1e30f;
            }
        }

        // Online softmax update; write P to smem
        float fac[4];
        #pragma unroll
        for (int i = 0; i < 4; i++) {
            float rmax = fmaxf(fmaxf(s[i][0], s[i][1]), fmaxf(s[i][2], s[i][3]));
            #pragma unroll
            for (int o = 1; o < 16; o <<= 1)
                rmax = fmaxf(rmax, __shfl_xor_sync(~0u, rmax, o));
            float mn = fmaxf(m[i], rmax);
            fac[i] = exp2f((m[i] - mn) * LOG2E);
            float4 p;
            p.x = exp2f((s[i][0] - mn) * LOG2E);
            p.y = exp2f((s[i][1] - mn) * LOG2E);
            p.z = exp2f((s[i][2] - mn) * LOG2E);
            p.w = exp2f((s[i][3] - mn) * LOG2E);
            *(float4*)&Ps[swz(qg * 4 + i, kg)] = p;
            float psum = p.x + p.y + p.z + p.w;
            #pragma unroll
            for (int o = 1; o < 16; o <<= 1)
                psum += __shfl_xor_sync(~0u, psum, o);
            l[i] = l[i] * fac[i] + psum;
            m[i] = mn;
        }
        __syncthreads();

        // Rescale O, then GEMM2: O += P x V  (thread = (qg, dg=kg))
        #pragma unroll
        for (int i = 0; i < 4; i++) {
            O[i].x *= fac[i]; O[i].y *= fac[i];
            O[i].z *= fac[i]; O[i].w *= fac[i];
        }
        #pragma unroll
        for (int jj4 = 0; jj4 < ATK / 4; jj4++) {
            float4 pv[4], vv[4];
            #pragma unroll
            for (int i = 0; i < 4; i++)
                pv[i] = *(const float4*)&Ps[swz(qg * 4 + i, jj4)];
            #pragma unroll
            for (int jj = 0; jj < 4; jj++)
                vv[jj] = *(const float4*)&Vs[swz(jj4 * 4 + jj, kg)];
            #pragma unroll
            for (int i = 0; i < 4; i++) {
                O[i].x += pv[i].x * vv[0].x + pv[i].y * vv[1].x
                        + pv[i].z * vv[2].x + pv[i].w * vv[3].x;
                O[i].y += pv[i].x * vv[0].y + pv[i].y * vv[1].y
                        + pv[i].z * vv[2].y + pv[i].w * vv[3].y;
                O[i].z += pv[i].x * vv[0].z + pv[i].y * vv[1].z
                        + pv[i].z * vv[2].z + pv[i].w * vv[3].z;
                O[i].w += pv[i].x * vv[0].w + pv[i].y * vv[1].w
                        + pv[i].z * vv[2].w + pv[i].w * vv[3].w;
            }
        }
    }

    // Epilogue
    #pragma unroll
    for (int i = 0; i < 4; i++) {
        float inv = 1.f / l[i];
        float4 v = O[i];
        v.x *= inv; v.y *= inv; v.z *= inv; v.w *= inv;
        *(float4*)(out + (size_t)(b * TSEQ + q0 + qg * 4 + i) * CDIM
                   + h * DHEAD + kg * 4) = v;
    }
}

// ---------------------------------------------------------------------------
// Launcher
// ---------------------------------------------------------------------------
extern "C" void kernel_launch(void* const* d_in, const int* in_sizes, int n_in,
                              void* d_out, int out_size) {
    const int*   tokens    = (const int*)  d_in[0];
    const float* tok_embed = (const float*)d_in[1];
    const float* pos_embed = (const float*)d_in[2];
    const float* ln1_w     = (const float*)d_in[3];
    const float* ln1_b     = (const float*)d_in[4];
    const float* qkv_w     = (const float*)d_in[5];
    const float* qkv_b     = (const float*)d_in[6];
    const float* proj_w    = (const float*)d_in[7];
    const float* proj_b    = (const float*)d_in[8];
    const float* ln2_w     = (const float*)d_in[9];
    const float* ln2_b     = (const float*)d_in[10];
    const float* fc_w      = (const float*)d_in[11];
    const float* fc_b      = (const float*)d_in[12];
    const float* fc2_w     = (const float*)d_in[13];
    const float* fc2_b     = (const float*)d_in[14];
    const float* lnf_w     = (const float*)d_in[15];
    const float* lnf_b     = (const float*)d_in[16];
    float* logits = (float*)d_out;

    float *x, *h, *qkv, *att, *ffn;
    cudaGetSymbolAddress((void**)&x,   g_x);
    cudaGetSymbolAddress((void**)&h,   g_h);
    cudaGetSymbolAddress((void**)&qkv, g_qkv);
    cudaGetSymbolAddress((void**)&att, g_att);
    cudaGetSymbolAddress((void**)&ffn, g_ffn);

    const int ATTN_SMEM = (ATQ * DHEAD + ATK * DHEAD * 2 + ATQ * DHEAD) * 4; // 96KB
    cudaFuncSetAttribute(attn_kernel,
                         cudaFuncAttributeMaxDynamicSharedMemorySize, ATTN_SMEM);

    embed_kernel<<<NROW, 256>>>(tokens, tok_embed, pos_embed, x);

    const int NB = NROW / BM;
    for (int l = 0; l < NLAYER; l++) {
        const float* l1w = ln1_w  + (size_t)l * CDIM;
        const float* l1b = ln1_b  + (size_t)l * CDIM;
        const float* qw  = qkv_w  + (size_t)l * 3 * CDIM * CDIM;
        const float* qb  = qkv_b  + (size_t)l * 3 * CDIM;
        const float* pw  = proj_w + (size_t)l * CDIM * CDIM;
        const float* pb  = proj_b + (size_t)l * CDIM;
        const float* l2w = ln2_w  + (size_t)l * CDIM;
        const float* l2b = ln2_b  + (size_t)l * CDIM;
        const float* fw  = fc_w   + (size_t)l * FFDIM * CDIM;
        const float* fb  = fc_b   + (size_t)l * FFDIM;
        const float* f2w = fc2_w  + (size_t)l * CDIM * FFDIM;
        const float* f2b = fc2_b  + (size_t)l * CDIM;

        ln_kernel<<<NROW, 256>>>(x, l1w, l1b, h);
        gemm_tf32_kernel<<<dim3(3 * CDIM / BN, NB), 256>>>(
            h, qw, qb, nullptr, qkv, NROW, 3 * CDIM, CDIM, 0);
        attn_kernel<<<dim3(TSEQ / ATQ, BSZ * NHEAD), 512, ATTN_SMEM>>>(qkv, att);
        gemm_tf32_kernel<<<dim3(CDIM / BN, NB), 256>>>(
            att, pw, pb, x, x, NROW, CDIM, CDIM, 0);
        ln_kernel<<<NROW, 256>>>(x, l2w, l2b, h);
        gemm_tf32_kernel<<<dim3(FFDIM / BN, NB), 256>>>(
            h, fw, fb, nullptr, ffn, NROW, FFDIM, CDIM, 1);
        gemm_tf32_kernel<<<dim3(CDIM / BN, NB), 256>>>(
            ffn, f2w, f2b, x, x, NROW, CDIM, FFDIM, 0);
    }

    ln_kernel<<<NROW, 256>>>(x, lnf_w, lnf_b, h);
    gemm_tf32_kernel<<<dim3((VOCAB + BN - 1) / BN, NB), 256>>>(
        h, tok_embed, nullptr, nullptr, logits, NROW, VOCAB, CDIM, 0);
}

// round 5
// speedup vs baseline: 2.9545x; 1.0003x over previous
#include <cuda_runtime.h>
#include <math.h>

// GPT-2 small config
#define BSZ   2
#define TSEQ  1024
#define CDIM  768
#define FFDIM 3072
#define NHEAD 12
#define NLAYER 12
#define DHEAD 64
#define VOCAB 50257
#define NROW  (BSZ * TSEQ)   // 2048

// ---------------------------------------------------------------------------
// Scratch (device globals — no allocation allowed)
// ---------------------------------------------------------------------------
__device__ float g_x  [NROW * CDIM];          // residual stream
__device__ float g_h  [NROW * CDIM];          // LN output
__device__ float g_qkv[NROW * 3 * CDIM];      // qkv projection
__device__ float g_att[NROW * CDIM];          // attention output
__device__ float g_ffn[NROW * FFDIM];         // FFN intermediate

// ---------------------------------------------------------------------------
// Embedding
// ---------------------------------------------------------------------------
__global__ void embed_kernel(const int* __restrict__ tokens,
                             const float* __restrict__ tok,
                             const float* __restrict__ pos,
                             float* __restrict__ x) {
    int n = blockIdx.x;
    int t = n % TSEQ;
    int tk = tokens[n];
    const float* tr = tok + (size_t)tk * CDIM;
    const float* pr = pos + (size_t)t * CDIM;
    float* xr = x + (size_t)n * CDIM;
    for (int c = threadIdx.x; c < CDIM; c += blockDim.x)
        xr[c] = tr[c] + pr[c];
}

// ---------------------------------------------------------------------------
// LayerNorm (block per row, 256 threads)
// ---------------------------------------------------------------------------
__global__ void ln_kernel(const float* __restrict__ x,
                          const float* __restrict__ w,
                          const float* __restrict__ b,
                          float* __restrict__ out) {
    int n = blockIdx.x;
    const float* xr = x + (size_t)n * CDIM;
    float s = 0.f, s2 = 0.f;
    for (int c = threadIdx.x; c < CDIM; c += blockDim.x) {
        float v = xr[c];
        s += v; s2 += v * v;
    }
    __shared__ float red[64];
    #pragma unroll
    for (int o = 16; o; o >>= 1) {
        s  += __shfl_xor_sync(~0u, s,  o);
        s2 += __shfl_xor_sync(~0u, s2, o);
    }
    int wid = threadIdx.x >> 5, lid = threadIdx.x & 31;
    if (lid == 0) { red[wid] = s; red[wid + 32] = s2; }
    __syncthreads();
    if (threadIdx.x == 0) {
        float ts = 0.f, ts2 = 0.f;
        int nw = blockDim.x >> 5;
        for (int i = 0; i < nw; i++) { ts += red[i]; ts2 += red[i + 32]; }
        float m = ts / CDIM;
        float var = ts2 / CDIM - m * m;
        red[0] = m;
        red[1] = rsqrtf(var + 1e-5f);
    }
    __syncthreads();
    float m = red[0], r = red[1];
    float* orow = out + (size_t)n * CDIM;
    for (int c = threadIdx.x; c < CDIM; c += blockDim.x)
        orow[c] = (xr[c] - m) * r * w[c] + b[c];
}

// ---------------------------------------------------------------------------
// TF32 helpers
// ---------------------------------------------------------------------------
__device__ __forceinline__ float f2tf32(float x) {
    asm("cvt.rna.tf32.f32 %0, %0;" : "+f"(x));
    return x;
}

__device__ __forceinline__ void mma_tf32(float (&d)[4],
                                         const float (&a)[4],
                                         const float (&b)[2]) {
    asm volatile(
        "mma.sync.aligned.m16n8k8.row.col.f32.tf32.tf32.f32 "
        "{%0,%1,%2,%3}, {%4,%5,%6,%7}, {%8,%9}, {%0,%1,%2,%3};\n"
        : "+f"(d[0]), "+f"(d[1]), "+f"(d[2]), "+f"(d[3])
        : "r"(__float_as_uint(a[0])), "r"(__float_as_uint(a[1])),
          "r"(__float_as_uint(a[2])), "r"(__float_as_uint(a[3])),
          "r"(__float_as_uint(b[0])), "r"(__float_as_uint(b[1])));
}

// ---------------------------------------------------------------------------
// TF32 NT GEMM (identical to R2 — known numerics)
// ---------------------------------------------------------------------------
#define BM 128
#define BN 128
#define BK 16
#define BK2 (BK + 2)

__global__ __launch_bounds__(256)
void gemm_tf32_kernel(const float* __restrict__ A,
                      const float* __restrict__ W,
                      const float* __restrict__ bias,
                      const float* __restrict__ res,
                      float* __restrict__ C,
                      int N, int M, int K, int gelu) {
    __shared__ float As[2][BM][BK2];
    __shared__ float Bs[2][BN][BK2];

    const int tid  = threadIdx.x;
    const int lane = tid & 31;
    const int wid  = tid >> 5;
    const int g    = lane >> 2;
    const int tig  = lane & 3;
    const int warp_m = wid >> 2;
    const int warp_n = wid & 3;
    const int bm = blockIdx.y * BM;
    const int bn = blockIdx.x * BN;

    const int lr0 = tid >> 2;
    const int lc4 = (tid & 3) * 4;

    float acc[4][4][4];
    #pragma unroll
    for (int mt = 0; mt < 4; mt++)
        #pragma unroll
        for (int nt = 0; nt < 4; nt++)
            #pragma unroll
            for (int r = 0; r < 4; r++) acc[mt][nt][r] = 0.f;

    const int KT = K / BK;

    {
        #pragma unroll
        for (int i = 0; i < 2; i++) {
            int r = lr0 + i * 64;
            float4 va = *(const float4*)(A + (size_t)(bm + r) * K + lc4);
            As[0][r][lc4 + 0] = f2tf32(va.x);
            As[0][r][lc4 + 1] = f2tf32(va.y);
            As[0][r][lc4 + 2] = f2tf32(va.z);
            As[0][r][lc4 + 3] = f2tf32(va.w);
            int m = bn + r;
            float4 vb = make_float4(0.f, 0.f, 0.f, 0.f);
            if (m < M) vb = *(const float4*)(W + (size_t)m * K + lc4);
            Bs[0][r][lc4 + 0] = f2tf32(vb.x);
            Bs[0][r][lc4 + 1] = f2tf32(vb.y);
            Bs[0][r][lc4 + 2] = f2tf32(vb.z);
            Bs[0][r][lc4 + 3] = f2tf32(vb.w);
        }
    }
    __syncthreads();

    int buf = 0;
    for (int it = 0; it < KT; it++) {
        float4 na[2], nb[2];
        const bool has_next = (it + 1 < KT);
        if (has_next) {
            int k0 = (it + 1) * BK;
            #pragma unroll
            for (int i = 0; i < 2; i++) {
                int r = lr0 + i * 64;
                na[i] = *(const float4*)(A + (size_t)(bm + r) * K + k0 + lc4);
                int m = bn + r;
                nb[i] = make_float4(0.f, 0.f, 0.f, 0.f);
                if (m < M) nb[i] = *(const float4*)(W + (size_t)m * K + k0 + lc4);
            }
        }

        #pragma unroll
        for (int ks = 0; ks < 2; ks++) {
            const int kb = ks * 8;
            float a[4][4], b[4][2];
            #pragma unroll
            for (int mt = 0; mt < 4; mt++) {
                int m0 = warp_m * 64 + mt * 16;
                a[mt][0] = As[buf][m0 + g    ][kb + tig    ];
                a[mt][1] = As[buf][m0 + g + 8][kb + tig    ];
                a[mt][2] = As[buf][m0 + g    ][kb + tig + 4];
                a[mt][3] = As[buf][m0 + g + 8][kb + tig + 4];
            }
            #pragma unroll
            for (int nt = 0; nt < 4; nt++) {
                int n0 = warp_n * 32 + nt * 8;
                b[nt][0] = Bs[buf][n0 + g][kb + tig    ];
                b[nt][1] = Bs[buf][n0 + g][kb + tig + 4];
            }
            #pragma unroll
            for (int mt = 0; mt < 4; mt++)
                #pragma unroll
                for (int nt = 0; nt < 4; nt++)
                    mma_tf32(acc[mt][nt], a[mt], b[nt]);
        }

        if (has_next) {
            int nbuf = buf ^ 1;
            #pragma unroll
            for (int i = 0; i < 2; i++) {
                int r = lr0 + i * 64;
                As[nbuf][r][lc4 + 0] = f2tf32(na[i].x);
                As[nbuf][r][lc4 + 1] = f2tf32(na[i].y);
                As[nbuf][r][lc4 + 2] = f2tf32(na[i].z);
                As[nbuf][r][lc4 + 3] = f2tf32(na[i].w);
                Bs[nbuf][r][lc4 + 0] = f2tf32(nb[i].x);
                Bs[nbuf][r][lc4 + 1] = f2tf32(nb[i].y);
                Bs[nbuf][r][lc4 + 2] = f2tf32(nb[i].z);
                Bs[nbuf][r][lc4 + 3] = f2tf32(nb[i].w);
            }
        }
        __syncthreads();
        buf ^= 1;
    }

    #pragma unroll
    for (int mt = 0; mt < 4; mt++) {
        #pragma unroll
        for (int nt = 0; nt < 4; nt++) {
            int col = bn + warp_n * 32 + nt * 8 + 2 * tig;
            #pragma unroll
            for (int rr = 0; rr < 2; rr++) {
                int row = bm + warp_m * 64 + mt * 16 + g + rr * 8;
                float v0 = acc[mt][nt][rr * 2 + 0];
                float v1 = acc[mt][nt][rr * 2 + 1];
                if (bias) { v0 += bias[col]; if (col + 1 < M) v1 += bias[col + 1]; }
                if (gelu) {
                    float u = v0;
                    v0 = 0.5f * u * (1.f + tanhf(0.7978845608028654f *
                                                 (u + 0.044715f * u * u * u)));
                    u = v1;
                    v1 = 0.5f * u * (1.f + tanhf(0.7978845608028654f *
                                                 (u + 0.044715f * u * u * u)));
                }
                size_t idx = (size_t)row * M + col;
                if (col + 1 < M) {
                    if (res) { v0 += res[idx]; v1 += res[idx + 1]; }
                    C[idx]     = v0;
                    C[idx + 1] = v1;
                } else if (col < M) {
                    if (res) v0 += res[idx];
                    C[idx] = v0;
                }
            }
        }
    }
}

// ---------------------------------------------------------------------------
// Flash-style tiled attention, fp32.
// Block: (b,h) x 128-query tile. 512 threads = 32 q-groups x 16 k/d-groups.
// Per thread: 4x4 S microtile (GEMM1), 4x4 O microtile (GEMM2).
// Smem tiles use XOR chunk swizzle: element (r, c) chunk cc=c/4 stored at
// chunk cc ^ ((r>>2)&15). Makes strided row reads conflict-free.
// ---------------------------------------------------------------------------
#define ATQ 128
#define ATK 64
#define LOG2E 1.44269504088896f

__device__ __forceinline__ int swz(int r, int dd) {   // dd = chunk index (c/4)
    return (r << 6) + (((dd) ^ ((r >> 2) & 15)) << 2);
}

__global__ __launch_bounds__(512)
void attn_kernel(const float* __restrict__ qkv, float* __restrict__ out) {
    extern __shared__ float sm[];
    float* Qs = sm;                       // 128 x 64 (swizzled)
    float* Ks = Qs + ATQ * DHEAD;         // 64 x 64
    float* Vs = Ks + ATK * DHEAD;         // 64 x 64
    float* Ps = Vs + ATK * DHEAD;         // 128 x 64

    const int qt = gridDim.x - 1 - blockIdx.x;   // heavy tiles first
    const int bh = blockIdx.y;
    const int b  = bh / NHEAD, h = bh % NHEAD;
    const int q0 = qt * ATQ;
    const int tid = threadIdx.x;
    const int qg = tid >> 4;     // 0..31
    const int kg = tid & 15;     // 0..15 (= dg in GEMM2)
    const size_t rstride = 3 * CDIM;

    // Load Q tile (pre-scaled by 1/sqrt(D))
    #pragma unroll
    for (int i = 0; i < 4; i++) {
        int f = i * 512 + tid;
        int r = f >> 4, cc = f & 15;
        float4 v = *(const float4*)(qkv + (size_t)(b * TSEQ + q0 + r) * rstride
                                    + h * DHEAD + cc * 4);
        v.x *= 0.125f; v.y *= 0.125f; v.z *= 0.125f; v.w *= 0.125f;
        *(float4*)&Qs[swz(r, cc)] = v;
    }

    float m[4], l[4];
    float4 O[4];
    #pragma unroll
    for (int i = 0; i < 4; i++) {
        m[i] = -1e30f; l[i] = 0.f; O[i] = make_float4(0.f, 0.f, 0.f, 0.f);
    }

    const int jtmax = (q0 + ATQ - 1) / ATK;
    for (int jt = 0; jt <= jtmax; jt++) {
        __syncthreads();
        // Stage K, V tiles (64 x 64 each)
        #pragma unroll
        for (int i = 0; i < 2; i++) {
            int f = i * 512 + tid;
            int r = f >> 4, cc = f & 15;
            const float* base = qkv + (size_t)(b * TSEQ + jt * ATK + r) * rstride
                                + h * DHEAD + cc * 4;
            *(float4*)&Ks[swz(r, cc)] = *(const float4*)(base + CDIM);
            *(float4*)&Vs[swz(r, cc)] = *(const float4*)(base + 2 * CDIM);
        }
        __syncthreads();

        // GEMM1: S(4q x 4k)
        float s[4][4];
        #pragma unroll
        for (int i = 0; i < 4; i++)
            #pragma unroll
            for (int j = 0; j < 4; j++) s[i][j] = 0.f;

        #pragma unroll
        for (int dd = 0; dd < DHEAD / 4; dd++) {
            float4 qv[4], kv[4];
            #pragma unroll
            for (int i = 0; i < 4; i++)
                qv[i] = *(const float4*)&Qs[swz(qg * 4 + i, dd)];
            #pragma unroll
            for (int j = 0; j < 4; j++)
                kv[j] = *(const float4*)&Ks[swz(kg * 4 + j, dd)];
            #pragma unroll
            for (int i = 0; i < 4; i++)
                #pragma unroll
                for (int j = 0; j < 4; j++)
                    s[i][j] += qv[i].x * kv[j].x + qv[i].y * kv[j].y
                             + qv[i].z * kv[j].z + qv[i].w * kv[j].w;
        }

        // Causal mask
        #pragma unroll
        for (int i = 0; i < 4; i++) {
            int qgl = q0 + qg * 4 + i;
            #pragma unroll
            for (int j = 0; j < 4; j++) {
                int jgl = jt * ATK + kg * 4 + j;
                if (jgl > qgl) s[i][j] = -1e30f;
            }
        }

        // Online softmax update; write P to smem
        float fac[4];
        #pragma unroll
        for (int i = 0; i < 4; i++) {
            float rmax = fmaxf(fmaxf(s[i][0], s[i][1]), fmaxf(s[i][2], s[i][3]));
            #pragma unroll
            for (int o = 1; o < 16; o <<= 1)
                rmax = fmaxf(rmax, __shfl_xor_sync(~0u, rmax, o));
            float mn = fmaxf(m[i], rmax);
            fac[i] = exp2f((m[i] - mn) * LOG2E);
            float4 p;
            p.x = exp2f((s[i][0] - mn) * LOG2E);
            p.y = exp2f((s[i][1] - mn) * LOG2E);
            p.z = exp2f((s[i][2] - mn) * LOG2E);
            p.w = exp2f((s[i][3] - mn) * LOG2E);
            *(float4*)&Ps[swz(qg * 4 + i, kg)] = p;
            float psum = p.x + p.y + p.z + p.w;
            #pragma unroll
            for (int o = 1; o < 16; o <<= 1)
                psum += __shfl_xor_sync(~0u, psum, o);
            l[i] = l[i] * fac[i] + psum;
            m[i] = mn;
        }
        __syncthreads();

        // Rescale O, then GEMM2: O += P x V  (thread = (qg, dg=kg))
        #pragma unroll
        for (int i = 0; i < 4; i++) {
            O[i].x *= fac[i]; O[i].y *= fac[i];
            O[i].z *= fac[i]; O[i].w *= fac[i];
        }
        #pragma unroll
        for (int jj4 = 0; jj4 < ATK / 4; jj4++) {
            float4 pv[4], vv[4];
            #pragma unroll
            for (int i = 0; i < 4; i++)
                pv[i] = *(const float4*)&Ps[swz(qg * 4 + i, jj4)];
            #pragma unroll
            for (int jj = 0; jj < 4; jj++)
                vv[jj] = *(const float4*)&Vs[swz(jj4 * 4 + jj, kg)];
            #pragma unroll
            for (int i = 0; i < 4; i++) {
                O[i].x += pv[i].x * vv[0].x + pv[i].y * vv[1].x
                        + pv[i].z * vv[2].x + pv[i].w * vv[3].x;
                O[i].y += pv[i].x * vv[0].y + pv[i].y * vv[1].y
                        + pv[i].z * vv[2].y + pv[i].w * vv[3].y;
                O[i].z += pv[i].x * vv[0].z + pv[i].y * vv[1].z
                        + pv[i].z * vv[2].z + pv[i].w * vv[3].z;
                O[i].w += pv[i].x * vv[0].w + pv[i].y * vv[1].w
                        + pv[i].z * vv[2].w + pv[i].w * vv[3].w;
            }
        }
    }

    // Epilogue
    #pragma unroll
    for (int i = 0; i < 4; i++) {
        float inv = 1.f / l[i];
        float4 v = O[i];
        v.x *= inv; v.y *= inv; v.z *= inv; v.w *= inv;
        *(float4*)(out + (size_t)(b * TSEQ + q0 + qg * 4 + i) * CDIM
                   + h * DHEAD + kg * 4) = v;
    }
}

// ---------------------------------------------------------------------------
// Launcher
// ---------------------------------------------------------------------------
extern "C" void kernel_launch(void* const* d_in, const int* in_sizes, int n_in,
                              void* d_out, int out_size) {
    const int*   tokens    = (const int*)  d_in[0];
    const float* tok_embed = (const float*)d_in[1];
    const float* pos_embed = (const float*)d_in[2];
    const float* ln1_w     = (const float*)d_in[3];
    const float* ln1_b     = (const float*)d_in[4];
    const float* qkv_w     = (const float*)d_in[5];
    const float* qkv_b     = (const float*)d_in[6];
    const float* proj_w    = (const float*)d_in[7];
    const float* proj_b    = (const float*)d_in[8];
    const float* ln2_w     = (const float*)d_in[9];
    const float* ln2_b     = (const float*)d_in[10];
    const float* fc_w      = (const float*)d_in[11];
    const float* fc_b      = (const float*)d_in[12];
    const float* fc2_w     = (const float*)d_in[13];
    const float* fc2_b     = (const float*)d_in[14];
    const float* lnf_w     = (const float*)d_in[15];
    const float* lnf_b     = (const float*)d_in[16];
    float* logits = (float*)d_out;

    float *x, *h, *qkv, *att, *ffn;
    cudaGetSymbolAddress((void**)&x,   g_x);
    cudaGetSymbolAddress((void**)&h,   g_h);
    cudaGetSymbolAddress((void**)&qkv, g_qkv);
    cudaGetSymbolAddress((void**)&att, g_att);
    cudaGetSymbolAddress((void**)&ffn, g_ffn);

    const int ATTN_SMEM = (ATQ * DHEAD + ATK * DHEAD * 2 + ATQ * DHEAD) * 4; // 96KB
    cudaFuncSetAttribute(attn_kernel,
                         cudaFuncAttributeMaxDynamicSharedMemorySize, ATTN_SMEM);

    embed_kernel<<<NROW, 256>>>(tokens, tok_embed, pos_embed, x);

    const int NB = NROW / BM;
    for (int l = 0; l < NLAYER; l++) {
        const float* l1w = ln1_w  + (size_t)l * CDIM;
        const float* l1b = ln1_b  + (size_t)l * CDIM;
        const float* qw  = qkv_w  + (size_t)l * 3 * CDIM * CDIM;
        const float* qb  = qkv_b  + (size_t)l * 3 * CDIM;
        const float* pw  = proj_w + (size_t)l * CDIM * CDIM;
        const float* pb  = proj_b + (size_t)l * CDIM;
        const float* l2w = ln2_w  + (size_t)l * CDIM;
        const float* l2b = ln2_b  + (size_t)l * CDIM;
        const float* fw  = fc_w   + (size_t)l * FFDIM * CDIM;
        const float* fb  = fc_b   + (size_t)l * FFDIM;
        const float* f2w = fc2_w  + (size_t)l * CDIM * FFDIM;
        const float* f2b = fc2_b  + (size_t)l * CDIM;

        ln_kernel<<<NROW, 256>>>(x, l1w, l1b, h);
        gemm_tf32_kernel<<<dim3(3 * CDIM / BN, NB), 256>>>(
            h, qw, qb, nullptr, qkv, NROW, 3 * CDIM, CDIM, 0);
        attn_kernel<<<dim3(TSEQ / ATQ, BSZ * NHEAD), 512, ATTN_SMEM>>>(qkv, att);
        gemm_tf32_kernel<<<dim3(CDIM / BN, NB), 256>>>(
            att, pw, pb, x, x, NROW, CDIM, CDIM, 0);
        ln_kernel<<<NROW, 256>>>(x, l2w, l2b, h);
        gemm_tf32_kernel<<<dim3(FFDIM / BN, NB), 256>>>(
            h, fw, fb, nullptr, ffn, NROW, FFDIM, CDIM, 1);
        gemm_tf32_kernel<<<dim3(CDIM / BN, NB), 256>>>(
            ffn, f2w, f2b, x, x, NROW, CDIM, FFDIM, 0);
    }

    ln_kernel<<<NROW, 256>>>(x, lnf_w, lnf_b, h);
    gemm_tf32_kernel<<<dim3((VOCAB + BN - 1) / BN, NB), 256>>>(
        h, tok_embed, nullptr, nullptr, logits, NROW, VOCAB, CDIM, 0);
}

// round 7
// speedup vs baseline: 3.9971x; 1.3529x over previous
#include <cuda_runtime.h>
#include <math.h>
#include <stdint.h>

// GPT-2 small config
#define BSZ   2
#define TSEQ  1024
#define CDIM  768
#define FFDIM 3072
#define NHEAD 12
#define NLAYER 12
#define DHEAD 64
#define VOCAB 50257
#define NROW  (BSZ * TSEQ)   // 2048

// ---------------------------------------------------------------------------
// Scratch (device globals — no allocation allowed)
// ---------------------------------------------------------------------------
__device__ float g_x  [NROW * CDIM];
__device__ float g_h  [NROW * CDIM];
__device__ float g_qkv[NROW * 3 * CDIM];
__device__ float g_att[NROW * CDIM];
__device__ float g_ffn[NROW * FFDIM];

// ---------------------------------------------------------------------------
// Helpers
// ---------------------------------------------------------------------------
__device__ __forceinline__ float f2tf32(float x) {
    asm("cvt.rna.tf32.f32 %0, %0;" : "+f"(x));
    return x;
}

__device__ __forceinline__ void mma_tf32(float (&d)[4],
                                         const float (&a)[4],
                                         const float (&b)[2]) {
    asm volatile(
        "mma.sync.aligned.m16n8k8.row.col.f32.tf32.tf32.f32 "
        "{%0,%1,%2,%3}, {%4,%5,%6,%7}, {%8,%9}, {%0,%1,%2,%3};\n"
        : "+f"(d[0]), "+f"(d[1]), "+f"(d[2]), "+f"(d[3])
        : "r"(__float_as_uint(a[0])), "r"(__float_as_uint(a[1])),
          "r"(__float_as_uint(a[2])), "r"(__float_as_uint(a[3])),
          "r"(__float_as_uint(b[0])), "r"(__float_as_uint(b[1])));
}

__device__ __forceinline__ uint32_t smem_u32(const void* p) {
    uint32_t a;
    asm("{ .reg .u64 t; cvta.to.shared.u64 t, %1; cvt.u32.u64 %0, t; }"
        : "=r"(a) : "l"(p));
    return a;
}

__device__ __forceinline__ void cpa16(uint32_t dst, const float* src, int sz) {
    asm volatile("cp.async.cg.shared.global [%0], [%1], 16, %2;"
                 :: "r"(dst), "l"(src), "r"(sz));
}
__device__ __forceinline__ void cpa_commit() {
    asm volatile("cp.async.commit_group;" ::: "memory");
}
template <int N>
__device__ __forceinline__ void cpa_wait() {
    asm volatile("cp.async.wait_group %0;" :: "n"(N) : "memory");
}

// ---------------------------------------------------------------------------
// Embedding
// ---------------------------------------------------------------------------
__global__ void embed_kernel(const int* __restrict__ tokens,
                             const float* __restrict__ tok,
                             const float* __restrict__ pos,
                             float* __restrict__ x) {
    int n = blockIdx.x;
    int t = n % TSEQ;
    int tk = tokens[n];
    const float* tr = tok + (size_t)tk * CDIM;
    const float* pr = pos + (size_t)t * CDIM;
    float* xr = x + (size_t)n * CDIM;
    for (int c = threadIdx.x; c < CDIM; c += blockDim.x)
        xr[c] = tr[c] + pr[c];
}

// ---------------------------------------------------------------------------
// LayerNorm (block per row, 256 threads). Output tf32-rounded (GEMM-A only).
// ---------------------------------------------------------------------------
__global__ void ln_kernel(const float* __restrict__ x,
                          const float* __restrict__ w,
                          const float* __restrict__ b,
                          float* __restrict__ out) {
    int n = blockIdx.x;
    const float* xr = x + (size_t)n * CDIM;
    float s = 0.f, s2 = 0.f;
    for (int c = threadIdx.x; c < CDIM; c += blockDim.x) {
        float v = xr[c];
        s += v; s2 += v * v;
    }
    __shared__ float red[64];
    #pragma unroll
    for (int o = 16; o; o >>= 1) {
        s  += __shfl_xor_sync(~0u, s,  o);
        s2 += __shfl_xor_sync(~0u, s2, o);
    }
    int wid = threadIdx.x >> 5, lid = threadIdx.x & 31;
    if (lid == 0) { red[wid] = s; red[wid + 32] = s2; }
    __syncthreads();
    if (threadIdx.x == 0) {
        float ts = 0.f, ts2 = 0.f;
        int nw = blockDim.x >> 5;
        for (int i = 0; i < nw; i++) { ts += red[i]; ts2 += red[i + 32]; }
        float m = ts / CDIM;
        float var = ts2 / CDIM - m * m;
        red[0] = m;
        red[1] = rsqrtf(var + 1e-5f);
    }
    __syncthreads();
    float m = red[0], r = red[1];
    float* orow = out + (size_t)n * CDIM;
    for (int c = threadIdx.x; c < CDIM; c += blockDim.x)
        orow[c] = f2tf32((xr[c] - m) * r * w[c] + b[c]);
}

// ---------------------------------------------------------------------------
// TF32 NT GEMM, cp.async 3-stage pipeline, BK=32.
// C[n,m] = sum_k A[n,k]*W[m,k] (+bias, +GELU, +residual).
// A pre-rounded to tf32 by producers; W rounded at fragment load.
// 256 threads = 8 warps (2x4), warp tile 64x32, m16n8k8.
// Smem: XOR-swizzled 128B rows, 3 stages x (A+B) = 96KB dynamic.
// ---------------------------------------------------------------------------
#define GSTAGE_F 8192                 // floats per stage (A 4096 + B 4096)
#define GSMEM_BYTES (3 * GSTAGE_F * 4)

__device__ __forceinline__ int gsw(int r, int k) {   // float index in 128x32 tile
    return r * 32 + (((k >> 2) ^ (r & 7)) << 2) + (k & 3);
}

__global__ __launch_bounds__(256)
void gemm_tf32_kernel(const float* __restrict__ A, const float* __restrict__ W,
                      const float* __restrict__ bias, const float* __restrict__ res,
                      float* __restrict__ C, int N, int M, int K, int gelu) {
    extern __shared__ __align__(16) float smf[];

    const int tid  = threadIdx.x;
    const int lane = tid & 31;
    const int wid  = tid >> 5;
    const int g    = lane >> 2;
    const int tig  = lane & 3;
    const int warp_m = wid >> 2;     // 0..1
    const int warp_n = wid & 3;      // 0..3
    const int bm = blockIdx.y * 128;
    const int bn = blockIdx.x * 128;
    const uint32_t sbase = smem_u32(smf);

    const int lr = tid >> 3;         // 0..31 (row step 32 per i)
    const int lc = tid & 7;          // chunk 0..7
    const uint32_t soff = (uint32_t)(lr * 32 + ((lc ^ (lr & 7)) << 2)) * 4u;

    float acc[4][4][4];
    #pragma unroll
    for (int mt = 0; mt < 4; mt++)
        #pragma unroll
        for (int nt = 0; nt < 4; nt++)
            #pragma unroll
            for (int r = 0; r < 4; r++) acc[mt][nt][r] = 0.f;

    const int KT = K / 32;

    // ---- issue loads for chunk j into stage j%3 ----
    auto issue = [&](int j) {
        const int k0 = j * 32;
        const uint32_t ab = sbase + (uint32_t)(j % 3) * GSTAGE_F * 4u;
        const uint32_t bb = ab + 4096u * 4u;
        #pragma unroll
        for (int i = 0; i < 4; i++) {
            int r = lr + i * 32;
            uint32_t rowoff = soff + (uint32_t)i * 32u * 32u * 4u;
            // swizzle depends on r&7 which is invariant under +32: soff valid
            cpa16(ab + rowoff, A + (size_t)(bm + r) * K + k0 + lc * 4, 16);
            int m = bn + r;
            const float* ws = W + (size_t)(m < M ? m : 0) * K + k0 + lc * 4;
            cpa16(bb + rowoff, ws, (m < M) ? 16 : 0);
        }
    };

    issue(0); cpa_commit();
    if (KT > 1) issue(1);
    cpa_commit();

    for (int it = 0; it < KT; it++) {
        if (it + 2 < KT) issue(it + 2);
        cpa_commit();
        cpa_wait<2>();
        __syncthreads();

        const float* Asm = smf + (it % 3) * GSTAGE_F;
        const float* Bsm = Asm + 4096;

        #pragma unroll
        for (int ks = 0; ks < 4; ks++) {
            const int kb = ks * 8;
            float a[4][4], b[4][2];
            #pragma unroll
            for (int mt = 0; mt < 4; mt++) {
                int m0 = warp_m * 64 + mt * 16;
                a[mt][0] = Asm[gsw(m0 + g,     kb + tig)];
                a[mt][1] = Asm[gsw(m0 + g + 8, kb + tig)];
                a[mt][2] = Asm[gsw(m0 + g,     kb + tig + 4)];
                a[mt][3] = Asm[gsw(m0 + g + 8, kb + tig + 4)];
            }
            #pragma unroll
            for (int nt = 0; nt < 4; nt++) {
                int n0 = warp_n * 32 + nt * 8;
                b[nt][0] = f2tf32(Bsm[gsw(n0 + g, kb + tig)]);
                b[nt][1] = f2tf32(Bsm[gsw(n0 + g, kb + tig + 4)]);
            }
            #pragma unroll
            for (int mt = 0; mt < 4; mt++)
                #pragma unroll
                for (int nt = 0; nt < 4; nt++)
                    mma_tf32(acc[mt][nt], a[mt], b[nt]);
        }
        __syncthreads();
    }

    // ---- epilogue (R3-validated mapping) ----
    #pragma unroll
    for (int mt = 0; mt < 4; mt++) {
        #pragma unroll
        for (int nt = 0; nt < 4; nt++) {
            int col = bn + warp_n * 32 + nt * 8 + 2 * tig;
            #pragma unroll
            for (int rr = 0; rr < 2; rr++) {
                int row = bm + warp_m * 64 + mt * 16 + g + rr * 8;
                float v0 = acc[mt][nt][rr * 2 + 0];
                float v1 = acc[mt][nt][rr * 2 + 1];
                if (bias) { v0 += bias[col]; if (col + 1 < M) v1 += bias[col + 1]; }
                if (gelu) {
                    float u = v0;
                    v0 = f2tf32(0.5f * u * (1.f + tanhf(0.7978845608028654f *
                                                 (u + 0.044715f * u * u * u))));
                    u = v1;
                    v1 = f2tf32(0.5f * u * (1.f + tanhf(0.7978845608028654f *
                                                 (u + 0.044715f * u * u * u))));
                }
                size_t idx = (size_t)row * M + col;
                if (col + 1 < M) {
                    if (res) { v0 += res[idx]; v1 += res[idx + 1]; }
                    C[idx]     = v0;
                    C[idx + 1] = v1;
                } else if (col < M) {
                    if (res) v0 += res[idx];
                    C[idx] = v0;
                }
            }
        }
    }
}

// ---------------------------------------------------------------------------
// Flash-style tiled attention, fp32. Output tf32-rounded (feeds proj GEMM A).
// ---------------------------------------------------------------------------
#define ATQ 128
#define ATK 64
#define LOG2E 1.44269504088896f

__device__ __forceinline__ int swz(int r, int dd) {
    return (r << 6) + (((dd) ^ ((r >> 2) & 15)) << 2);
}

__global__ __launch_bounds__(512)
void attn_kernel(const float* __restrict__ qkv, float* __restrict__ out) {
    extern __shared__ float sm[];
    float* Qs = sm;
    float* Ks = Qs + ATQ * DHEAD;
    float* Vs = Ks + ATK * DHEAD;
    float* Ps = Vs + ATK * DHEAD;

    const int qt = gridDim.x - 1 - blockIdx.x;
    const int bh = blockIdx.y;
    const int b  = bh / NHEAD, h = bh % NHEAD;
    const int q0 = qt * ATQ;
    const int tid = threadIdx.x;
    const int qg = tid >> 4;
    const int kg = tid & 15;
    const size_t rstride = 3 * CDIM;

    #pragma unroll
    for (int i = 0; i < 4; i++) {
        int f = i * 512 + tid;
        int r = f >> 4, cc = f & 15;
        float4 v = *(const float4*)(qkv + (size_t)(b * TSEQ + q0 + r) * rstride
                                    + h * DHEAD + cc * 4);
        v.x *= 0.125f; v.y *= 0.125f; v.z *= 0.125f; v.w *= 0.125f;
        *(float4*)&Qs[swz(r, cc)] = v;
    }

    float m[4], l[4];
    float4 O[4];
    #pragma unroll
    for (int i = 0; i < 4; i++) {
        m[i] = -1e30f; l[i] = 0.f; O[i] = make_float4(0.f, 0.f, 0.f, 0.f);
    }

    const int jtmax = (q0 + ATQ - 1) / ATK;
    for (int jt = 0; jt <= jtmax; jt++) {
        __syncthreads();
        #pragma unroll
        for (int i = 0; i < 2; i++) {
            int f = i * 512 + tid;
            int r = f >> 4, cc = f & 15;
            const float* base = qkv + (size_t)(b * TSEQ + jt * ATK + r) * rstride
                                + h * DHEAD + cc * 4;
            *(float4*)&Ks[swz(r, cc)] = *(const float4*)(base + CDIM);
            *(float4*)&Vs[swz(r, cc)] = *(const float4*)(base + 2 * CDIM);
        }
        __syncthreads();

        float s[4][4];
        #pragma unroll
        for (int i = 0; i < 4; i++)
            #pragma unroll
            for (int j = 0; j < 4; j++) s[i][j] = 0.f;

        #pragma unroll
        for (int dd = 0; dd < DHEAD / 4; dd++) {
            float4 qv[4], kv[4];
            #pragma unroll
            for (int i = 0; i < 4; i++)
                qv[i] = *(const float4*)&Qs[swz(qg * 4 + i, dd)];
            #pragma unroll
            for (int j = 0; j < 4; j++)
                kv[j] = *(const float4*)&Ks[swz(kg * 4 + j, dd)];
            #pragma unroll
            for (int i = 0; i < 4; i++)
                #pragma unroll
                for (int j = 0; j < 4; j++)
                    s[i][j] += qv[i].x * kv[j].x + qv[i].y * kv[j].y
                             + qv[i].z * kv[j].z + qv[i].w * kv[j].w;
        }

        #pragma unroll
        for (int i = 0; i < 4; i++) {
            int qgl = q0 + qg * 4 + i;
            #pragma unroll
            for (int j = 0; j < 4; j++) {
                int jgl = jt * ATK + kg * 4 + j;
                if (jgl > qgl) s[i][j] = -1e30f;
            }
        }

        float fac[4];
        #pragma unroll
        for (int i = 0; i < 4; i++) {
            float rmax = fmaxf(fmaxf(s[i][0], s[i][1]), fmaxf(s[i][2], s[i][3]));
            #pragma unroll
            for (int o = 1; o < 16; o <<= 1)
                rmax = fmaxf(rmax, __shfl_xor_sync(~0u, rmax, o));
            float mn = fmaxf(m[i], rmax);
            fac[i] = exp2f((m[i] - mn) * LOG2E);
            float4 p;
            p.x = exp2f((s[i][0] - mn) * LOG2E);
            p.y = exp2f((s[i][1] - mn) * LOG2E);
            p.z = exp2f((s[i][2] - mn) * LOG2E);
            p.w = exp2f((s[i][3] - mn) * LOG2E);
            *(float4*)&Ps[swz(qg * 4 + i, kg)] = p;
            float psum = p.x + p.y + p.z + p.w;
            #pragma unroll
            for (int o = 1; o < 16; o <<= 1)
                psum += __shfl_xor_sync(~0u, psum, o);
            l[i] = l[i] * fac[i] + psum;
            m[i] = mn;
        }
        __syncthreads();

        #pragma unroll
        for (int i = 0; i < 4; i++) {
            O[i].x *= fac[i]; O[i].y *= fac[i];
            O[i].z *= fac[i]; O[i].w *= fac[i];
        }
        #pragma unroll
        for (int jj4 = 0; jj4 < ATK / 4; jj4++) {
            float4 pv[4], vv[4];
            #pragma unroll
            for (int i = 0; i < 4; i++)
                pv[i] = *(const float4*)&Ps[swz(qg * 4 + i, jj4)];
            #pragma unroll
            for (int jj = 0; jj < 4; jj++)
                vv[jj] = *(const float4*)&Vs[swz(jj4 * 4 + jj, kg)];
            #pragma unroll
            for (int i = 0; i < 4; i++) {
                O[i].x += pv[i].x * vv[0].x + pv[i].y * vv[1].x
                        + pv[i].z * vv[2].x + pv[i].w * vv[3].x;
                O[i].y += pv[i].x * vv[0].y + pv[i].y * vv[1].y
                        + pv[i].z * vv[2].y + pv[i].w * vv[3].y;
                O[i].z += pv[i].x * vv[0].z + pv[i].y * vv[1].z
                        + pv[i].z * vv[2].z + pv[i].w * vv[3].z;
                O[i].w += pv[i].x * vv[0].w + pv[i].y * vv[1].w
                        + pv[i].z * vv[2].w + pv[i].w * vv[3].w;
            }
        }
    }

    #pragma unroll
    for (int i = 0; i < 4; i++) {
        float inv = 1.f / l[i];
        float4 v = O[i];
        v.x = f2tf32(v.x * inv); v.y = f2tf32(v.y * inv);
        v.z = f2tf32(v.z * inv); v.w = f2tf32(v.w * inv);
        *(float4*)(out + (size_t)(b * TSEQ + q0 + qg * 4 + i) * CDIM
                   + h * DHEAD + kg * 4) = v;
    }
}

// ---------------------------------------------------------------------------
// Launcher
// ---------------------------------------------------------------------------
extern "C" void kernel_launch(void* const* d_in, const int* in_sizes, int n_in,
                              void* d_out, int out_size) {
    const int*   tokens    = (const int*)  d_in[0];
    const float* tok_embed = (const float*)d_in[1];
    const float* pos_embed = (const float*)d_in[2];
    const float* ln1_w     = (const float*)d_in[3];
    const float* ln1_b     = (const float*)d_in[4];
    const float* qkv_w     = (const float*)d_in[5];
    const float* qkv_b     = (const float*)d_in[6];
    const float* proj_w    = (const float*)d_in[7];
    const float* proj_b    = (const float*)d_in[8];
    const float* ln2_w     = (const float*)d_in[9];
    const float* ln2_b     = (const float*)d_in[10];
    const float* fc_w      = (const float*)d_in[11];
    const float* fc_b      = (const float*)d_in[12];
    const float* fc2_w     = (const float*)d_in[13];
    const float* fc2_b     = (const float*)d_in[14];
    const float* lnf_w     = (const float*)d_in[15];
    const float* lnf_b     = (const float*)d_in[16];
    float* logits = (float*)d_out;

    float *x, *h, *qkv, *att, *ffn;
    cudaGetSymbolAddress((void**)&x,   g_x);
    cudaGetSymbolAddress((void**)&h,   g_h);
    cudaGetSymbolAddress((void**)&qkv, g_qkv);
    cudaGetSymbolAddress((void**)&att, g_att);
    cudaGetSymbolAddress((void**)&ffn, g_ffn);

    const int ATTN_SMEM = (ATQ * DHEAD + ATK * DHEAD * 2 + ATQ * DHEAD) * 4;
    cudaFuncSetAttribute(attn_kernel,
                         cudaFuncAttributeMaxDynamicSharedMemorySize, ATTN_SMEM);
    cudaFuncSetAttribute(gemm_tf32_kernel,
                         cudaFuncAttributeMaxDynamicSharedMemorySize, GSMEM_BYTES);

    embed_kernel<<<NROW, 256>>>(tokens, tok_embed, pos_embed, x);

    const int NB = NROW / 128;   // 16 row-blocks
    for (int l = 0; l < NLAYER; l++) {
        const float* l1w = ln1_w  + (size_t)l * CDIM;
        const float* l1b = ln1_b  + (size_t)l * CDIM;
        const float* qw  = qkv_w  + (size_t)l * 3 * CDIM * CDIM;
        const float* qb  = qkv_b  + (size_t)l * 3 * CDIM;
        const float* pw  = proj_w + (size_t)l * CDIM * CDIM;
        const float* pb  = proj_b + (size_t)l * CDIM;
        const float* l2w = ln2_w  + (size_t)l * CDIM;
        const float* l2b = ln2_b  + (size_t)l * CDIM;
        const float* fw  = fc_w   + (size_t)l * FFDIM * CDIM;
        const float* fb  = fc_b   + (size_t)l * FFDIM;
        const float* f2w = fc2_w  + (size_t)l * CDIM * FFDIM;
        const float* f2b = fc2_b  + (size_t)l * CDIM;

        ln_kernel<<<NROW, 256>>>(x, l1w, l1b, h);
        gemm_tf32_kernel<<<dim3(3 * CDIM / 128, NB), 256, GSMEM_BYTES>>>(
            h, qw, qb, nullptr, qkv, NROW, 3 * CDIM, CDIM, 0);
        attn_kernel<<<dim3(TSEQ / ATQ, BSZ * NHEAD), 512, ATTN_SMEM>>>(qkv, att);
        gemm_tf32_kernel<<<dim3(CDIM / 128, NB), 256, GSMEM_BYTES>>>(
            att, pw, pb, x, x, NROW, CDIM, CDIM, 0);
        ln_kernel<<<NROW, 256>>>(x, l2w, l2b, h);
        gemm_tf32_kernel<<<dim3(FFDIM / 128, NB), 256, GSMEM_BYTES>>>(
            h, fw, fb, nullptr, ffn, NROW, FFDIM, CDIM, 1);
        gemm_tf32_kernel<<<dim3(CDIM / 128, NB), 256, GSMEM_BYTES>>>(
            ffn, f2w, f2b, x, x, NROW, CDIM, FFDIM, 0);
    }

    ln_kernel<<<NROW, 256>>>(x, lnf_w, lnf_b, h);
    gemm_tf32_kernel<<<dim3((VOCAB + 127) / 128, NB), 256, GSMEM_BYTES>>>(
        h, tok_embed, nullptr, nullptr, logits, NROW, VOCAB, CDIM, 0);
}

// round 8
// speedup vs baseline: 5.1083x; 1.2780x over previous
#include <cuda_runtime.h>
#include <math.h>
#include <stdint.h>

// GPT-2 small config
#define BSZ   2
#define TSEQ  1024
#define CDIM  768
#define FFDIM 3072
#define NHEAD 12
#define NLAYER 12
#define DHEAD 64
#define VOCAB 50257
#define NROW  (BSZ * TSEQ)   // 2048

// ---------------------------------------------------------------------------
// Scratch (device globals — no allocation allowed)
// ---------------------------------------------------------------------------
__device__ float g_x  [NROW * CDIM];
__device__ float g_h  [NROW * CDIM];
__device__ float g_qkv[NROW * 3 * CDIM];
__device__ float g_att[NROW * CDIM];
__device__ float g_ffn[NROW * FFDIM];

// ---------------------------------------------------------------------------
// Helpers
// ---------------------------------------------------------------------------
__device__ __forceinline__ float f2tf32(float x) {
    asm("cvt.rna.tf32.f32 %0, %0;" : "+f"(x));
    return x;
}

__device__ __forceinline__ void mma_tf32(float (&d)[4],
                                         const float (&a)[4],
                                         const float (&b)[2]) {
    asm volatile(
        "mma.sync.aligned.m16n8k8.row.col.f32.tf32.tf32.f32 "
        "{%0,%1,%2,%3}, {%4,%5,%6,%7}, {%8,%9}, {%0,%1,%2,%3};\n"
        : "+f"(d[0]), "+f"(d[1]), "+f"(d[2]), "+f"(d[3])
        : "r"(__float_as_uint(a[0])), "r"(__float_as_uint(a[1])),
          "r"(__float_as_uint(a[2])), "r"(__float_as_uint(a[3])),
          "r"(__float_as_uint(b[0])), "r"(__float_as_uint(b[1])));
}

__device__ __forceinline__ uint32_t smem_u32(const void* p) {
    uint32_t a;
    asm("{ .reg .u64 t; cvta.to.shared.u64 t, %1; cvt.u32.u64 %0, t; }"
        : "=r"(a) : "l"(p));
    return a;
}

__device__ __forceinline__ void cpa16(uint32_t dst, const float* src, int sz) {
    asm volatile("cp.async.cg.shared.global [%0], [%1], 16, %2;"
                 :: "r"(dst), "l"(src), "r"(sz));
}
__device__ __forceinline__ void cpa_commit() {
    asm volatile("cp.async.commit_group;" ::: "memory");
}
template <int N>
__device__ __forceinline__ void cpa_wait() {
    asm volatile("cp.async.wait_group %0;" :: "n"(N) : "memory");
}

// ---------------------------------------------------------------------------
// Embedding
// ---------------------------------------------------------------------------
__global__ void embed_kernel(const int* __restrict__ tokens,
                             const float* __restrict__ tok,
                             const float* __restrict__ pos,
                             float* __restrict__ x) {
    int n = blockIdx.x;
    int t = n % TSEQ;
    int tk = tokens[n];
    const float* tr = tok + (size_t)tk * CDIM;
    const float* pr = pos + (size_t)t * CDIM;
    float* xr = x + (size_t)n * CDIM;
    for (int c = threadIdx.x; c < CDIM; c += blockDim.x)
        xr[c] = tr[c] + pr[c];
}

// ---------------------------------------------------------------------------
// LayerNorm (block per row, 256 threads). Output tf32-rounded (GEMM-A only).
// ---------------------------------------------------------------------------
__global__ void ln_kernel(const float* __restrict__ x,
                          const float* __restrict__ w,
                          const float* __restrict__ b,
                          float* __restrict__ out) {
    int n = blockIdx.x;
    const float* xr = x + (size_t)n * CDIM;
    float s = 0.f, s2 = 0.f;
    for (int c = threadIdx.x; c < CDIM; c += blockDim.x) {
        float v = xr[c];
        s += v; s2 += v * v;
    }
    __shared__ float red[64];
    #pragma unroll
    for (int o = 16; o; o >>= 1) {
        s  += __shfl_xor_sync(~0u, s,  o);
        s2 += __shfl_xor_sync(~0u, s2, o);
    }
    int wid = threadIdx.x >> 5, lid = threadIdx.x & 31;
    if (lid == 0) { red[wid] = s; red[wid + 32] = s2; }
    __syncthreads();
    if (threadIdx.x == 0) {
        float ts = 0.f, ts2 = 0.f;
        int nw = blockDim.x >> 5;
        for (int i = 0; i < nw; i++) { ts += red[i]; ts2 += red[i + 32]; }
        float m = ts / CDIM;
        float var = ts2 / CDIM - m * m;
        red[0] = m;
        red[1] = rsqrtf(var + 1e-5f);
    }
    __syncthreads();
    float m = red[0], r = red[1];
    float* orow = out + (size_t)n * CDIM;
    for (int c = threadIdx.x; c < CDIM; c += blockDim.x)
        orow[c] = f2tf32((xr[c] - m) * r * w[c] + b[c]);
}

// ---------------------------------------------------------------------------
// TF32 NT GEMM, cp.async 3-stage pipeline, BK=32 (unchanged from R6 — at
// ~93% of legacy tensor-pipe roofline).
// ---------------------------------------------------------------------------
#define GSTAGE_F 8192
#define GSMEM_BYTES (3 * GSTAGE_F * 4)

__device__ __forceinline__ int gsw(int r, int k) {
    return r * 32 + (((k >> 2) ^ (r & 7)) << 2) + (k & 3);
}

__global__ __launch_bounds__(256)
void gemm_tf32_kernel(const float* __restrict__ A, const float* __restrict__ W,
                      const float* __restrict__ bias, const float* __restrict__ res,
                      float* __restrict__ C, int N, int M, int K, int gelu) {
    extern __shared__ __align__(16) float smf[];

    const int tid  = threadIdx.x;
    const int lane = tid & 31;
    const int wid  = tid >> 5;
    const int g    = lane >> 2;
    const int tig  = lane & 3;
    const int warp_m = wid >> 2;
    const int warp_n = wid & 3;
    const int bm = blockIdx.y * 128;
    const int bn = blockIdx.x * 128;
    const uint32_t sbase = smem_u32(smf);

    const int lr = tid >> 3;
    const int lc = tid & 7;
    const uint32_t soff = (uint32_t)(lr * 32 + ((lc ^ (lr & 7)) << 2)) * 4u;

    float acc[4][4][4];
    #pragma unroll
    for (int mt = 0; mt < 4; mt++)
        #pragma unroll
        for (int nt = 0; nt < 4; nt++)
            #pragma unroll
            for (int r = 0; r < 4; r++) acc[mt][nt][r] = 0.f;

    const int KT = K / 32;

    auto issue = [&](int j) {
        const int k0 = j * 32;
        const uint32_t ab = sbase + (uint32_t)(j % 3) * GSTAGE_F * 4u;
        const uint32_t bb = ab + 4096u * 4u;
        #pragma unroll
        for (int i = 0; i < 4; i++) {
            int r = lr + i * 32;
            uint32_t rowoff = soff + (uint32_t)i * 32u * 32u * 4u;
            cpa16(ab + rowoff, A + (size_t)(bm + r) * K + k0 + lc * 4, 16);
            int m = bn + r;
            const float* ws = W + (size_t)(m < M ? m : 0) * K + k0 + lc * 4;
            cpa16(bb + rowoff, ws, (m < M) ? 16 : 0);
        }
    };

    issue(0); cpa_commit();
    if (KT > 1) issue(1);
    cpa_commit();

    for (int it = 0; it < KT; it++) {
        if (it + 2 < KT) issue(it + 2);
        cpa_commit();
        cpa_wait<2>();
        __syncthreads();

        const float* Asm = smf + (it % 3) * GSTAGE_F;
        const float* Bsm = Asm + 4096;

        #pragma unroll
        for (int ks = 0; ks < 4; ks++) {
            const int kb = ks * 8;
            float a[4][4], b[4][2];
            #pragma unroll
            for (int mt = 0; mt < 4; mt++) {
                int m0 = warp_m * 64 + mt * 16;
                a[mt][0] = Asm[gsw(m0 + g,     kb + tig)];
                a[mt][1] = Asm[gsw(m0 + g + 8, kb + tig)];
                a[mt][2] = Asm[gsw(m0 + g,     kb + tig + 4)];
                a[mt][3] = Asm[gsw(m0 + g + 8, kb + tig + 4)];
            }
            #pragma unroll
            for (int nt = 0; nt < 4; nt++) {
                int n0 = warp_n * 32 + nt * 8;
                b[nt][0] = f2tf32(Bsm[gsw(n0 + g, kb + tig)]);
                b[nt][1] = f2tf32(Bsm[gsw(n0 + g, kb + tig + 4)]);
            }
            #pragma unroll
            for (int mt = 0; mt < 4; mt++)
                #pragma unroll
                for (int nt = 0; nt < 4; nt++)
                    mma_tf32(acc[mt][nt], a[mt], b[nt]);
        }
        __syncthreads();
    }

    #pragma unroll
    for (int mt = 0; mt < 4; mt++) {
        #pragma unroll
        for (int nt = 0; nt < 4; nt++) {
            int col = bn + warp_n * 32 + nt * 8 + 2 * tig;
            #pragma unroll
            for (int rr = 0; rr < 2; rr++) {
                int row = bm + warp_m * 64 + mt * 16 + g + rr * 8;
                float v0 = acc[mt][nt][rr * 2 + 0];
                float v1 = acc[mt][nt][rr * 2 + 1];
                if (bias) { v0 += bias[col]; if (col + 1 < M) v1 += bias[col + 1]; }
                if (gelu) {
                    float u = v0;
                    v0 = f2tf32(0.5f * u * (1.f + tanhf(0.7978845608028654f *
                                                 (u + 0.044715f * u * u * u))));
                    u = v1;
                    v1 = f2tf32(0.5f * u * (1.f + tanhf(0.7978845608028654f *
                                                 (u + 0.044715f * u * u * u))));
                }
                size_t idx = (size_t)row * M + col;
                if (col + 1 < M) {
                    if (res) { v0 += res[idx]; v1 += res[idx + 1]; }
                    C[idx]     = v0;
                    C[idx + 1] = v1;
                } else if (col < M) {
                    if (res) v0 += res[idx];
                    C[idx] = v0;
                }
            }
        }
    }
}

// ---------------------------------------------------------------------------
// Tensor-core flash attention (tf32 mma).
// Block: 128 threads (4 warps), q-tile 64, k-tile 64. Warp owns a 16-row
// q band; softmax reductions are quad shuffles. S->A fragment conversion
// for P@V done in-register via quad shuffles (no P smem).
// Smem: Qs,Ks,Vt 64x64 each, unified swizzle tswz (conflict-free for
// fragment reads, row stores, and V-transpose stores).
// ---------------------------------------------------------------------------
#define ATQ 64
#define ATK 64
#define LOG2E 1.44269504088896f
#define ATTN_SMEM (3 * 64 * 64 * 4)

__device__ __forceinline__ int tswz(int r, int c) {
    return r * 64 + ((((c >> 2) ^ ((r + (r >> 4)) & 15))) << 2) + (c & 3);
}

__global__ __launch_bounds__(128)
void attn_kernel(const float* __restrict__ qkv, float* __restrict__ out) {
    extern __shared__ float sm[];
    float* Qs = sm;            // [64][64] swizzled
    float* Ks = sm + 4096;     // [64][64]
    float* Vt = sm + 8192;     // [d][j] transposed V

    const int qt = gridDim.x - 1 - blockIdx.x;   // heavy tiles first
    const int bh = blockIdx.y;
    const int b  = bh / NHEAD, h = bh % NHEAD;
    const int q0 = qt * ATQ;
    const int tid  = threadIdx.x;
    const int lane = tid & 31;
    const int wid  = tid >> 5;     // 0..3
    const int g    = lane >> 2;    // 0..7
    const int tig  = lane & 3;     // 0..3
    const int m0   = wid * 16;     // q-row band base
    const size_t rstride = 3 * CDIM;
    const float qsc = 0.125f * LOG2E;   // scores in log2 domain

    // ---- stage Q (scaled + tf32) ----
    #pragma unroll
    for (int i = 0; i < 8; i++) {
        int f = i * 128 + tid;
        int r = f >> 4, c4 = (f & 15) * 4;
        float4 v = *(const float4*)(qkv + (size_t)(b * TSEQ + q0 + r) * rstride
                                    + h * DHEAD + c4);
        v.x = f2tf32(v.x * qsc); v.y = f2tf32(v.y * qsc);
        v.z = f2tf32(v.z * qsc); v.w = f2tf32(v.w * qsc);
        *(float4*)&Qs[tswz(r, c4)] = v;
    }

    float mrow[2] = {-1e30f, -1e30f};
    float lrow[2] = {0.f, 0.f};
    float O[8][4];
    #pragma unroll
    for (int nt = 0; nt < 8; nt++)
        #pragma unroll
        for (int r = 0; r < 4; r++) O[nt][r] = 0.f;

    const int src1 = (g << 2) | (tig >> 1);
    const int src2 = src1 + 2;
    const bool odd = (tig & 1);

    for (int jt = 0; jt <= qt; jt++) {
        __syncthreads();
        // ---- stage K rows (tf32) ----
        #pragma unroll
        for (int i = 0; i < 8; i++) {
            int f = i * 128 + tid;
            int r = f >> 4, c4 = (f & 15) * 4;
            float4 v = *(const float4*)(qkv + (size_t)(b * TSEQ + jt * ATK + r) * rstride
                                        + CDIM + h * DHEAD + c4);
            v.x = f2tf32(v.x); v.y = f2tf32(v.y);
            v.z = f2tf32(v.z); v.w = f2tf32(v.w);
            *(float4*)&Ks[tswz(r, c4)] = v;
        }
        // ---- stage V transposed (tf32): Vt[d][j] = V[j][d] ----
        #pragma unroll
        for (int i = 0; i < 8; i++) {
            int f = i * 128 + tid;
            int j = f >> 4, d0 = (f & 15) * 4;
            float4 v = *(const float4*)(qkv + (size_t)(b * TSEQ + jt * ATK + j) * rstride
                                        + 2 * CDIM + h * DHEAD + d0);
            Vt[tswz(d0 + 0, j)] = f2tf32(v.x);
            Vt[tswz(d0 + 1, j)] = f2tf32(v.y);
            Vt[tswz(d0 + 2, j)] = f2tf32(v.z);
            Vt[tswz(d0 + 3, j)] = f2tf32(v.w);
        }
        __syncthreads();

        // ---- GEMM1: S = Q K^T  (warp tile 16 x 64) ----
        float s[8][4];
        #pragma unroll
        for (int nt = 0; nt < 8; nt++)
            #pragma unroll
            for (int r = 0; r < 4; r++) s[nt][r] = 0.f;

        #pragma unroll
        for (int ks = 0; ks < 8; ks++) {
            const int kb = ks * 8;
            float a[4];
            a[0] = Qs[tswz(m0 + g,     kb + tig)];
            a[1] = Qs[tswz(m0 + g + 8, kb + tig)];
            a[2] = Qs[tswz(m0 + g,     kb + tig + 4)];
            a[3] = Qs[tswz(m0 + g + 8, kb + tig + 4)];
            #pragma unroll
            for (int nt = 0; nt < 8; nt++) {
                float bb[2];
                bb[0] = Ks[tswz(nt * 8 + g, kb + tig)];
                bb[1] = Ks[tswz(nt * 8 + g, kb + tig + 4)];
                mma_tf32(s[nt], a, bb);
            }
        }

        // ---- causal mask + online softmax ----
        const int r0 = q0 + m0 + g, r1 = r0 + 8;
        const int jb = jt * ATK;
        float rx0 = -1e30f, rx1 = -1e30f;
        #pragma unroll
        for (int nt = 0; nt < 8; nt++) {
            int c0 = jb + nt * 8 + 2 * tig;
            if (c0     > r0) s[nt][0] = -1e30f;
            if (c0 + 1 > r0) s[nt][1] = -1e30f;
            if (c0     > r1) s[nt][2] = -1e30f;
            if (c0 + 1 > r1) s[nt][3] = -1e30f;
            rx0 = fmaxf(rx0, fmaxf(s[nt][0], s[nt][1]));
            rx1 = fmaxf(rx1, fmaxf(s[nt][2], s[nt][3]));
        }
        rx0 = fmaxf(rx0, __shfl_xor_sync(~0u, rx0, 1));
        rx0 = fmaxf(rx0, __shfl_xor_sync(~0u, rx0, 2));
        rx1 = fmaxf(rx1, __shfl_xor_sync(~0u, rx1, 1));
        rx1 = fmaxf(rx1, __shfl_xor_sync(~0u, rx1, 2));

        float mn0 = fmaxf(mrow[0], rx0);
        float mn1 = fmaxf(mrow[1], rx1);
        float fac0 = exp2f(mrow[0] - mn0);
        float fac1 = exp2f(mrow[1] - mn1);
        float ps0 = 0.f, ps1 = 0.f;
        #pragma unroll
        for (int nt = 0; nt < 8; nt++) {
            float p0 = f2tf32(exp2f(s[nt][0] - mn0));
            float p1 = f2tf32(exp2f(s[nt][1] - mn0));
            float p2 = f2tf32(exp2f(s[nt][2] - mn1));
            float p3 = f2tf32(exp2f(s[nt][3] - mn1));
            s[nt][0] = p0; s[nt][1] = p1; s[nt][2] = p2; s[nt][3] = p3;
            ps0 += p0 + p1; ps1 += p2 + p3;
        }
        ps0 += __shfl_xor_sync(~0u, ps0, 1);
        ps0 += __shfl_xor_sync(~0u, ps0, 2);
        ps1 += __shfl_xor_sync(~0u, ps1, 1);
        ps1 += __shfl_xor_sync(~0u, ps1, 2);
        lrow[0] = lrow[0] * fac0 + ps0;
        lrow[1] = lrow[1] * fac1 + ps1;
        mrow[0] = mn0; mrow[1] = mn1;

        #pragma unroll
        for (int nt = 0; nt < 8; nt++) {
            O[nt][0] *= fac0; O[nt][1] *= fac0;
            O[nt][2] *= fac1; O[nt][3] *= fac1;
        }

        // ---- GEMM2: O += P V  (A-frags via in-register quad shuffles) ----
        #pragma unroll
        for (int ks = 0; ks < 8; ks++) {
            float v0 = __shfl_sync(~0u, s[ks][0], src1);
            float v1 = __shfl_sync(~0u, s[ks][1], src1);
            float v2 = __shfl_sync(~0u, s[ks][2], src1);
            float v3 = __shfl_sync(~0u, s[ks][3], src1);
            float w0 = __shfl_sync(~0u, s[ks][0], src2);
            float w1 = __shfl_sync(~0u, s[ks][1], src2);
            float w2 = __shfl_sync(~0u, s[ks][2], src2);
            float w3 = __shfl_sync(~0u, s[ks][3], src2);
            float a[4];
            a[0] = odd ? v1 : v0;   // P[g][kb+tig]
            a[1] = odd ? v3 : v2;   // P[g+8][kb+tig]
            a[2] = odd ? w1 : w0;   // P[g][kb+tig+4]
            a[3] = odd ? w3 : w2;   // P[g+8][kb+tig+4]
            const int kb = ks * 8;
            #pragma unroll
            for (int nt = 0; nt < 8; nt++) {
                float bb[2];
                bb[0] = Vt[tswz(nt * 8 + g, kb + tig)];
                bb[1] = Vt[tswz(nt * 8 + g, kb + tig + 4)];
                mma_tf32(O[nt], a, bb);
            }
        }
    }

    // ---- epilogue: normalize + store (tf32-rounded; feeds proj GEMM A) ----
    float inv0 = 1.f / lrow[0];
    float inv1 = 1.f / lrow[1];
    float* o0 = out + (size_t)(b * TSEQ + q0 + m0 + g) * CDIM + h * DHEAD;
    float* o1 = o0 + 8 * CDIM;
    #pragma unroll
    for (int nt = 0; nt < 8; nt++) {
        int c = nt * 8 + 2 * tig;
        float2 u0 = make_float2(f2tf32(O[nt][0] * inv0), f2tf32(O[nt][1] * inv0));
        float2 u1 = make_float2(f2tf32(O[nt][2] * inv1), f2tf32(O[nt][3] * inv1));
        *(float2*)(o0 + c) = u0;
        *(float2*)(o1 + c) = u1;
    }
}

// ---------------------------------------------------------------------------
// Launcher
// ---------------------------------------------------------------------------
extern "C" void kernel_launch(void* const* d_in, const int* in_sizes, int n_in,
                              void* d_out, int out_size) {
    const int*   tokens    = (const int*)  d_in[0];
    const float* tok_embed = (const float*)d_in[1];
    const float* pos_embed = (const float*)d_in[2];
    const float* ln1_w     = (const float*)d_in[3];
    const float* ln1_b     = (const float*)d_in[4];
    const float* qkv_w     = (const float*)d_in[5];
    const float* qkv_b     = (const float*)d_in[6];
    const float* proj_w    = (const float*)d_in[7];
    const float* proj_b    = (const float*)d_in[8];
    const float* ln2_w     = (const float*)d_in[9];
    const float* ln2_b     = (const float*)d_in[10];
    const float* fc_w      = (const float*)d_in[11];
    const float* fc_b      = (const float*)d_in[12];
    const float* fc2_w     = (const float*)d_in[13];
    const float* fc2_b     = (const float*)d_in[14];
    const float* lnf_w     = (const float*)d_in[15];
    const float* lnf_b     = (const float*)d_in[16];
    float* logits = (float*)d_out;

    float *x, *h, *qkv, *att, *ffn;
    cudaGetSymbolAddress((void**)&x,   g_x);
    cudaGetSymbolAddress((void**)&h,   g_h);
    cudaGetSymbolAddress((void**)&qkv, g_qkv);
    cudaGetSymbolAddress((void**)&att, g_att);
    cudaGetSymbolAddress((void**)&ffn, g_ffn);

    cudaFuncSetAttribute(attn_kernel,
                         cudaFuncAttributeMaxDynamicSharedMemorySize, ATTN_SMEM);
    cudaFuncSetAttribute(gemm_tf32_kernel,
                         cudaFuncAttributeMaxDynamicSharedMemorySize, GSMEM_BYTES);

    embed_kernel<<<NROW, 256>>>(tokens, tok_embed, pos_embed, x);

    const int NB = NROW / 128;   // 16 row-blocks
    for (int l = 0; l < NLAYER; l++) {
        const float* l1w = ln1_w  + (size_t)l * CDIM;
        const float* l1b = ln1_b  + (size_t)l * CDIM;
        const float* qw  = qkv_w  + (size_t)l * 3 * CDIM * CDIM;
        const float* qb  = qkv_b  + (size_t)l * 3 * CDIM;
        const float* pw  = proj_w + (size_t)l * CDIM * CDIM;
        const float* pb  = proj_b + (size_t)l * CDIM;
        const float* l2w = ln2_w  + (size_t)l * CDIM;
        const float* l2b = ln2_b  + (size_t)l * CDIM;
        const float* fw  = fc_w   + (size_t)l * FFDIM * CDIM;
        const float* fb  = fc_b   + (size_t)l * FFDIM;
        const float* f2w = fc2_w  + (size_t)l * CDIM * FFDIM;
        const float* f2b = fc2_b  + (size_t)l * CDIM;

        ln_kernel<<<NROW, 256>>>(x, l1w, l1b, h);
        gemm_tf32_kernel<<<dim3(3 * CDIM / 128, NB), 256, GSMEM_BYTES>>>(
            h, qw, qb, nullptr, qkv, NROW, 3 * CDIM, CDIM, 0);
        attn_kernel<<<dim3(TSEQ / ATQ, BSZ * NHEAD), 128, ATTN_SMEM>>>(qkv, att);
        gemm_tf32_kernel<<<dim3(CDIM / 128, NB), 256, GSMEM_BYTES>>>(
            att, pw, pb, x, x, NROW, CDIM, CDIM, 0);
        ln_kernel<<<NROW, 256>>>(x, l2w, l2b, h);
        gemm_tf32_kernel<<<dim3(FFDIM / 128, NB), 256, GSMEM_BYTES>>>(
            h, fw, fb, nullptr, ffn, NROW, FFDIM, CDIM, 1);
        gemm_tf32_kernel<<<dim3(CDIM / 128, NB), 256, GSMEM_BYTES>>>(
            ffn, f2w, f2b, x, x, NROW, CDIM, FFDIM, 0);
    }

    ln_kernel<<<NROW, 256>>>(x, lnf_w, lnf_b, h);
    gemm_tf32_kernel<<<dim3((VOCAB + 127) / 128, NB), 256, GSMEM_BYTES>>>(
        h, tok_embed, nullptr, nullptr, logits, NROW, VOCAB, CDIM, 0);
}